// round 7
// baseline (speedup 1.0000x reference)
#include <cuda_runtime.h>
#include <cuda_bf16.h>
#include <cstddef>

// Problem sizes: B=256, T=512, I=256, H=512, 4H=2048
// Layouts: g_XP [T, B, 4H], g_H [T, B, H]  (t-major: each step = contiguous slab)

__device__ float g_XP[(size_t)512 * 256 * 2048]; // 1 GiB input projections (reused per layer)
__device__ float g_H [(size_t)512 * 256 * 512];  // 256 MiB hidden states (reused per layer)
__device__ float g_C [256 * 512];                // [B,H] cell state
__device__ float g_Z [256 * 512];                // zeros (h_{-1}); never written
__device__ unsigned g_bar;                       // grid barrier counter

__device__ __forceinline__ unsigned pack2(__nv_bfloat16 a, __nv_bfloat16 b) {
    __nv_bfloat162 t = __halves2bfloat162(a, b);
    return *reinterpret_cast<unsigned*>(&t);
}

// Split float4 into hi/lo bf16x2 words (k-even in low half) for bf16x3 GEMM.
__device__ __forceinline__ void split4(float4 v, unsigned& h0, unsigned& h1,
                                       unsigned& l0, unsigned& l1) {
    __nv_bfloat16 bx = __float2bfloat16(v.x), by = __float2bfloat16(v.y);
    __nv_bfloat16 bz = __float2bfloat16(v.z), bw = __float2bfloat16(v.w);
    h0 = pack2(bx, by);
    h1 = pack2(bz, bw);
    l0 = pack2(__float2bfloat16(v.x - __bfloat162float(bx)),
               __float2bfloat16(v.y - __bfloat162float(by)));
    l1 = pack2(__float2bfloat16(v.z - __bfloat162float(bz)),
               __float2bfloat16(v.w - __bfloat162float(bw)));
}

__device__ __forceinline__ void mma_bf16(float* d, const unsigned* a, const unsigned* b) {
    asm volatile(
        "mma.sync.aligned.m16n8k16.row.col.f32.bf16.bf16.f32 "
        "{%0,%1,%2,%3}, {%4,%5,%6,%7}, {%8,%9}, {%0,%1,%2,%3};\n"
        : "+f"(d[0]), "+f"(d[1]), "+f"(d[2]), "+f"(d[3])
        : "r"(a[0]), "r"(a[1]), "r"(a[2]), "r"(a[3]), "r"(b[0]), "r"(b[1]));
}

__device__ __forceinline__ float sigf(float x)   { return 1.f / (1.f + __expf(-x)); }
__device__ __forceinline__ float tanhf_(float x) { return 2.f / (1.f + __expf(-2.f * x)) - 1.f; }

// ---------------------------------------------------------------------------
// proj_kernel: out[t,b,0:2048] = A_row(b,t)[0:K] @ W[2048,K]^T + bias1 + bias2
// (unchanged from R6 — it validated on hardware)
// ---------------------------------------------------------------------------
__global__ void __launch_bounds__(256) proj_kernel(
    const float* __restrict__ A, int sAb, int sAt, int K,
    const float* __restrict__ W,
    const float* __restrict__ bias1, const float* __restrict__ bias2,
    float* __restrict__ out)
{
    __shared__ unsigned AsH[2][128][9], AsL[2][128][9];
    __shared__ unsigned WsH[2][64][9],  WsL[2][64][9];

    const int tid  = threadIdx.x;
    const int lane = tid & 31;
    const int warp = tid >> 5;
    const int wr = warp >> 1, wc = warp & 1;
    const int m0 = blockIdx.x * 128;
    const int bb = m0 >> 9;        // batch index (shared by whole tile)
    const int tt0 = m0 & 511;      // first timestep of tile
    const int n0 = blockIdx.y * 64;

    const int ar0 = tid >> 2, ac = tid & 3;
    const int wrow = tid >> 2;

    const float* Ar0 = A + (size_t)bb * sAb + (size_t)(tt0 + ar0) * sAt;
    const float* Ar1 = A + (size_t)bb * sAb + (size_t)(tt0 + ar0 + 64) * sAt;
    const float* Wr  = W + (size_t)(n0 + wrow) * K;

    const int nkt = K >> 4;

    float acc[2][4][4];
#pragma unroll
    for (int f = 0; f < 2; ++f)
#pragma unroll
        for (int n = 0; n < 4; ++n)
#pragma unroll
            for (int i = 0; i < 4; ++i) acc[f][n][i] = 0.f;

    float4 ra0 = *(const float4*)(Ar0 + ac * 4);
    float4 ra1 = *(const float4*)(Ar1 + ac * 4);
    float4 rw  = *(const float4*)(Wr  + ac * 4);
    {
        unsigned h0, h1, l0, l1;
        split4(ra0, h0, h1, l0, l1);
        AsH[0][ar0][2*ac] = h0; AsH[0][ar0][2*ac+1] = h1;
        AsL[0][ar0][2*ac] = l0; AsL[0][ar0][2*ac+1] = l1;
        split4(ra1, h0, h1, l0, l1);
        AsH[0][ar0+64][2*ac] = h0; AsH[0][ar0+64][2*ac+1] = h1;
        AsL[0][ar0+64][2*ac] = l0; AsL[0][ar0+64][2*ac+1] = l1;
        split4(rw, h0, h1, l0, l1);
        WsH[0][wrow][2*ac] = h0; WsH[0][wrow][2*ac+1] = h1;
        WsL[0][wrow][2*ac] = l0; WsL[0][wrow][2*ac+1] = l1;
    }
    __syncthreads();

    int cur = 0;
    for (int kt = 0; kt < nkt; ++kt) {
        const bool pf = (kt + 1 < nkt);
        if (pf) {
            const int k1 = (kt + 1) * 16;
            ra0 = *(const float4*)(Ar0 + k1 + ac * 4);
            ra1 = *(const float4*)(Ar1 + k1 + ac * 4);
            rw  = *(const float4*)(Wr  + k1 + ac * 4);
        }
        const int r = lane >> 2, c = lane & 3;
        unsigned ah[2][4], al[2][4], bh[4][2], bl[4][2];
#pragma unroll
        for (int f = 0; f < 2; ++f) {
            const int mb = wr * 32 + f * 16;
            ah[f][0] = AsH[cur][mb + r    ][c];
            ah[f][1] = AsH[cur][mb + r + 8][c];
            ah[f][2] = AsH[cur][mb + r    ][c + 4];
            ah[f][3] = AsH[cur][mb + r + 8][c + 4];
            al[f][0] = AsL[cur][mb + r    ][c];
            al[f][1] = AsL[cur][mb + r + 8][c];
            al[f][2] = AsL[cur][mb + r    ][c + 4];
            al[f][3] = AsL[cur][mb + r + 8][c + 4];
        }
#pragma unroll
        for (int n = 0; n < 4; ++n) {
            const int nb = wc * 32 + n * 8 + r;
            bh[n][0] = WsH[cur][nb][c];
            bh[n][1] = WsH[cur][nb][c + 4];
            bl[n][0] = WsL[cur][nb][c];
            bl[n][1] = WsL[cur][nb][c + 4];
        }
#pragma unroll
        for (int f = 0; f < 2; ++f)
#pragma unroll
            for (int n = 0; n < 4; ++n) {
                mma_bf16(acc[f][n], ah[f], bh[n]);
                mma_bf16(acc[f][n], ah[f], bl[n]);
                mma_bf16(acc[f][n], al[f], bh[n]);
            }
        if (pf) {
            const int nxt = cur ^ 1;
            unsigned h0, h1, l0, l1;
            split4(ra0, h0, h1, l0, l1);
            AsH[nxt][ar0][2*ac] = h0; AsH[nxt][ar0][2*ac+1] = h1;
            AsL[nxt][ar0][2*ac] = l0; AsL[nxt][ar0][2*ac+1] = l1;
            split4(ra1, h0, h1, l0, l1);
            AsH[nxt][ar0+64][2*ac] = h0; AsH[nxt][ar0+64][2*ac+1] = h1;
            AsL[nxt][ar0+64][2*ac] = l0; AsL[nxt][ar0+64][2*ac+1] = l1;
            split4(rw, h0, h1, l0, l1);
            WsH[nxt][wrow][2*ac] = h0; WsH[nxt][wrow][2*ac+1] = h1;
            WsL[nxt][wrow][2*ac] = l0; WsL[nxt][wrow][2*ac+1] = l1;
        }
        __syncthreads();
        cur ^= 1;
    }

    const int r = lane >> 2, c2 = (lane & 3) * 2;
#pragma unroll
    for (int f = 0; f < 2; ++f) {
#pragma unroll
        for (int n = 0; n < 4; ++n) {
            const int tloc = tt0 + wr * 32 + f * 16 + r;
            const int col = n0 + wc * 32 + n * 8 + c2;
            const float bb0 = bias1[col] + bias2[col];
            const float bb1 = bias1[col + 1] + bias2[col + 1];
            float* o0 = out + (size_t)tloc * 524288 + (size_t)bb * 2048 + col;
            o0[0]    = acc[f][n][0] + bb0;
            o0[1]    = acc[f][n][1] + bb1;
            float* o1 = out + (size_t)(tloc + 8) * 524288 + (size_t)bb * 2048 + col;
            o1[0]    = acc[f][n][2] + bb0;
            o1[1]    = acc[f][n][3] + bb1;
        }
    }
}

// ---------------------------------------------------------------------------
// lstm_persist_kernel: ALL 512 timesteps of one layer in a single launch.
// Grid: 128 CTAs (co-resident, 1/SM), 256 threads. CTA owns 64 batch rows x
// 16 hidden units (64 gate cols). W_hh tile is loaded into SMEM ONCE (hi/lo
// bf16 split), then the kernel loops over t with a grid-wide spin barrier
// between steps. h[t] slabs are t-major so every step reads fresh addresses
// (no stale-L1 hazard).
// SMEM (dynamic, ~173 KB): WsH[32][64][9], WsL[32][64][9],
//                          AsH[2][64][9], AsL[2][64][9], Gs[64][65]
// ---------------------------------------------------------------------------
#define WH(kt,row,c) WsH[(kt)*576 + (row)*9 + (c)]
#define WL(kt,row,c) WsL[(kt)*576 + (row)*9 + (c)]
#define AH(bf,row,c) AsH[(bf)*576 + (row)*9 + (c)]
#define AL(bf,row,c) AsL[(bf)*576 + (row)*9 + (c)]

__global__ void __launch_bounds__(256) lstm_persist_kernel(
    const float* __restrict__ h0,      // [B,H] zeros, row stride 512
    const float* __restrict__ Whh,     // [2048, 512]
    const float* __restrict__ XP,      // [T,B,4H]
    float* __restrict__ Hbase,         // [T,B,H]
    float* __restrict__ cbuf,          // [B*H]
    unsigned* __restrict__ bar)
{
    extern __shared__ unsigned smem[];
    unsigned* WsH = smem;                    // 18432
    unsigned* WsL = WsH + 18432;             // 18432
    unsigned* AsH = WsL + 18432;             // 1152
    unsigned* AsL = AsH + 1152;              // 1152
    float*    Gs  = (float*)(AsL + 1152);    // 64*65

    const int tid  = threadIdx.x;
    const int lane = tid & 31;
    const int warp = tid >> 5;
    const int wr = warp >> 1, wc = warp & 1;
    const int m0 = (blockIdx.x & 3) * 64;    // batch base
    const int j0 = (blockIdx.x >> 2) * 16;   // hidden-unit base

    const int ar = tid >> 2, ac = tid & 3;
    const int wl = tid >> 2;                              // local gate col 0..63
    const int grow = ((wl >> 4) << 9) + j0 + (wl & 15);   // gate row in W_hh

    // --- load W tile into SMEM once (hi/lo split) ---
    {
        const float* Wr = Whh + (size_t)grow * 512;
        for (int kt = 0; kt < 32; ++kt) {
            float4 w = *(const float4*)(Wr + kt * 16 + ac * 4);
            unsigned h0w, h1w, l0w, l1w;
            split4(w, h0w, h1w, l0w, l1w);
            WH(kt, wl, 2*ac)   = h0w; WH(kt, wl, 2*ac+1) = h1w;
            WL(kt, wl, 2*ac)   = l0w; WL(kt, wl, 2*ac+1) = l1w;
        }
    }
    __syncthreads();

    const int r = lane >> 2, c = lane & 3;
    const int mb = wr * 16;

    for (int t = 0; t < 512; ++t) {
        const float* hp = t ? (Hbase + (size_t)(t - 1) * 131072) : h0;
        const float* Ar = hp + (size_t)(m0 + ar) * 512;

        float acc[4][4];
#pragma unroll
        for (int n = 0; n < 4; ++n)
#pragma unroll
            for (int i = 0; i < 4; ++i) acc[n][i] = 0.f;

        // prologue: k-tile 0
        float4 ra = *(const float4*)(Ar + ac * 4);
        {
            unsigned h0w, h1w, l0w, l1w;
            split4(ra, h0w, h1w, l0w, l1w);
            AH(0, ar, 2*ac) = h0w; AH(0, ar, 2*ac+1) = h1w;
            AL(0, ar, 2*ac) = l0w; AL(0, ar, 2*ac+1) = l1w;
        }
        __syncthreads();

        int cur = 0;
#pragma unroll 4
        for (int kt = 0; kt < 32; ++kt) {
            const bool pf = (kt + 1 < 32);
            if (pf)
                ra = *(const float4*)(Ar + (kt + 1) * 16 + ac * 4);

            unsigned ah[4], al[4], bh[4][2], bl[4][2];
            ah[0] = AH(cur, mb + r,     c);
            ah[1] = AH(cur, mb + r + 8, c);
            ah[2] = AH(cur, mb + r,     c + 4);
            ah[3] = AH(cur, mb + r + 8, c + 4);
            al[0] = AL(cur, mb + r,     c);
            al[1] = AL(cur, mb + r + 8, c);
            al[2] = AL(cur, mb + r,     c + 4);
            al[3] = AL(cur, mb + r + 8, c + 4);
#pragma unroll
            for (int n = 0; n < 4; ++n) {
                const int nb = wc * 32 + n * 8 + r;
                bh[n][0] = WH(kt, nb, c);
                bh[n][1] = WH(kt, nb, c + 4);
                bl[n][0] = WL(kt, nb, c);
                bl[n][1] = WL(kt, nb, c + 4);
            }
#pragma unroll
            for (int n = 0; n < 4; ++n) {
                mma_bf16(acc[n], ah, bh[n]);
                mma_bf16(acc[n], ah, bl[n]);
                mma_bf16(acc[n], al, bh[n]);
            }
            if (pf) {
                const int nxt = cur ^ 1;
                unsigned h0w, h1w, l0w, l1w;
                split4(ra, h0w, h1w, l0w, l1w);
                AH(nxt, ar, 2*ac) = h0w; AH(nxt, ar, 2*ac+1) = h1w;
                AL(nxt, ar, 2*ac) = l0w; AL(nxt, ar, 2*ac+1) = l1w;
            }
            __syncthreads();
            cur ^= 1;
        }

        // stage gates into SMEM
        {
            const int c2 = (lane & 3) * 2;
            const int rl = wr * 16 + r;
#pragma unroll
            for (int n = 0; n < 4; ++n) {
                const int cl = wc * 32 + n * 8 + c2;
                Gs[rl * 65 + cl]           = acc[n][0];
                Gs[rl * 65 + cl + 1]       = acc[n][1];
                Gs[(rl + 8) * 65 + cl]     = acc[n][2];
                Gs[(rl + 8) * 65 + cl + 1] = acc[n][3];
            }
        }
        __syncthreads();

        // gate nonlinearities + c/h update
        {
            const float* xpt = XP + (size_t)t * 524288;
            float* hout = Hbase + (size_t)t * 131072;
            const int j  = tid & 15;
            const int mr = tid >> 4;
#pragma unroll
            for (int p = 0; p < 4; ++p) {
                const int m = mr + p * 16;
                const int b = m0 + m;
                const int jg = j0 + j;
                const float* xr = xpt + (size_t)b * 2048;
                const float xi = xr[jg]        + Gs[m * 65 + j];
                const float xf = xr[512 + jg]  + Gs[m * 65 + j + 16];
                const float xg = xr[1024 + jg] + Gs[m * 65 + j + 32];
                const float xo = xr[1536 + jg] + Gs[m * 65 + j + 48];
                const float ig = sigf(xi), fg = sigf(xf), gg = tanhf_(xg), og = sigf(xo);
                const size_t ci = (size_t)b * 512 + jg;
                const float cv = fg * cbuf[ci] + ig * gg;
                cbuf[ci] = cv;
                hout[(size_t)b * 512 + jg] = og * tanhf_(cv);
            }
        }

        // grid-wide barrier (monotonic counter; reset to 0 before each launch)
        __threadfence();
        __syncthreads();
        if (tid == 0) {
            atomicAdd(bar, 1u);
            const unsigned target = 128u * (unsigned)(t + 1);
            while (*(volatile unsigned*)bar < target) { }
        }
        __syncthreads();
    }
}

// ---------------------------------------------------------------------------
__global__ void zero_kernel(float* __restrict__ p, int n, unsigned* __restrict__ bar) {
    const int i = blockIdx.x * 256 + threadIdx.x;
    if (i < n) p[i] = 0.f;
    if (i == 0) *bar = 0u;
}

__global__ void final_kernel(
    const float* __restrict__ hlast,   // [B,H] slab, row stride 512
    const float* __restrict__ Wl, const float* __restrict__ bl,
    float* __restrict__ y)
{
    const int b = blockIdx.x * 8 + (threadIdx.x >> 5);
    const int lane = threadIdx.x & 31;
    const float* hr = hlast + (size_t)b * 512;
    float s = 0.f;
    for (int k = lane; k < 512; k += 32) s += hr[k] * Wl[k];
#pragma unroll
    for (int o = 16; o; o >>= 1) s += __shfl_xor_sync(0xffffffffu, s, o);
    if (lane == 0) y[b] = s + bl[0];
}

// ---------------------------------------------------------------------------
extern "C" void kernel_launch(void* const* d_in, const int* in_sizes, int n_in,
                              void* d_out, int out_size)
{
    const float* X     = (const float*)d_in[0];
    const float* W_ih0 = (const float*)d_in[1];
    const float* W_hh0 = (const float*)d_in[2];
    const float* b_ih0 = (const float*)d_in[3];
    const float* b_hh0 = (const float*)d_in[4];
    const float* W_ih1 = (const float*)d_in[5];
    const float* W_hh1 = (const float*)d_in[6];
    const float* b_ih1 = (const float*)d_in[7];
    const float* b_hh1 = (const float*)d_in[8];
    const float* W_lin = (const float*)d_in[9];
    const float* b_lin = (const float*)d_in[10];
    float* y = (float*)d_out;

    float *XP, *Hb, *Cb, *Zb;
    unsigned* bar;
    cudaGetSymbolAddress((void**)&XP, g_XP);
    cudaGetSymbolAddress((void**)&Hb, g_H);
    cudaGetSymbolAddress((void**)&Cb, g_C);
    cudaGetSymbolAddress((void**)&Zb, g_Z);
    cudaGetSymbolAddress((void**)&bar, g_bar);

    const int PERSIST_SMEM = (18432 * 2 + 1152 * 2 + 64 * 65) * 4; // 173,312 B
    static bool attr_done = false;
    if (!attr_done) {
        cudaFuncSetAttribute(lstm_persist_kernel,
                             cudaFuncAttributeMaxDynamicSharedMemorySize, PERSIST_SMEM);
        attr_done = true;
    }

    // Layer 0
    zero_kernel<<<512, 256>>>(Cb, 256 * 512, bar);
    proj_kernel<<<dim3(1024, 32), 256>>>(X, 131072, 256, 256, W_ih0, b_ih0, b_hh0, XP);
    lstm_persist_kernel<<<128, 256, PERSIST_SMEM>>>(Zb, W_hh0, XP, Hb, Cb, bar);

    // Layer 1
    proj_kernel<<<dim3(1024, 32), 256>>>(Hb, 512, 131072, 512, W_ih1, b_ih1, b_hh1, XP);
    zero_kernel<<<512, 256>>>(Cb, 256 * 512, bar);
    lstm_persist_kernel<<<128, 256, PERSIST_SMEM>>>(Zb, W_hh1, XP, Hb, Cb, bar);

    final_kernel<<<32, 256>>>(Hb + (size_t)511 * 131072, W_lin, b_lin, y);
}

// round 9
// speedup vs baseline: 1.0386x; 1.0386x over previous
#include <cuda_runtime.h>
#include <cuda_bf16.h>
#include <cstdint>
#include <cstddef>

// Problem sizes: B=256, T=512, I=256, H=512, 4H=2048
// Layouts: g_XP [T,B,4H], g_H [T,B,H] fp32, g_HP [T,B,H] packed (hi,lo bf16)

__device__ float    g_XP[(size_t)512 * 256 * 2048]; // 1 GiB input projections
__device__ float    g_H [(size_t)512 * 256 * 512];  // fp32 hidden states
__device__ unsigned g_HP[(size_t)512 * 256 * 512];  // packed bf16 hi/lo hidden states
__device__ float    g_C [256 * 512];                // cell state
__device__ float    g_Z [256 * 512];                // zeros (h_{-1}; also packed view)
__device__ unsigned g_bar;                          // grid barrier counter

__device__ __forceinline__ unsigned pack2(__nv_bfloat16 a, __nv_bfloat16 b) {
    __nv_bfloat162 t = __halves2bfloat162(a, b);
    return *reinterpret_cast<unsigned*>(&t);
}

__device__ __forceinline__ void split4(float4 v, unsigned& h0, unsigned& h1,
                                       unsigned& l0, unsigned& l1) {
    __nv_bfloat16 bx = __float2bfloat16(v.x), by = __float2bfloat16(v.y);
    __nv_bfloat16 bz = __float2bfloat16(v.z), bw = __float2bfloat16(v.w);
    h0 = pack2(bx, by);
    h1 = pack2(bz, bw);
    l0 = pack2(__float2bfloat16(v.x - __bfloat162float(bx)),
               __float2bfloat16(v.y - __bfloat162float(by)));
    l1 = pack2(__float2bfloat16(v.z - __bfloat162float(bz)),
               __float2bfloat16(v.w - __bfloat162float(bw)));
}

__device__ __forceinline__ void mma_bf16(float* d, const unsigned* a, const unsigned* b) {
    asm volatile(
        "mma.sync.aligned.m16n8k16.row.col.f32.bf16.bf16.f32 "
        "{%0,%1,%2,%3}, {%4,%5,%6,%7}, {%8,%9}, {%0,%1,%2,%3};\n"
        : "+f"(d[0]), "+f"(d[1]), "+f"(d[2]), "+f"(d[3])
        : "r"(a[0]), "r"(a[1]), "r"(a[2]), "r"(a[3]), "r"(b[0]), "r"(b[1]));
}

__device__ __forceinline__ float sigf(float x)   { return 1.f / (1.f + __expf(-x)); }
__device__ __forceinline__ float tanhf_(float x) { return 2.f / (1.f + __expf(-2.f * x)) - 1.f; }

// ---------------------------------------------------------------------------
// proj_kernel: out[t,b,0:2048] = A_row(b,t)[0:K] @ W[2048,K]^T + bias1 + bias2
// (unchanged — validated on hardware in R7)
// ---------------------------------------------------------------------------
__global__ void __launch_bounds__(256) proj_kernel(
    const float* __restrict__ A, int sAb, int sAt, int K,
    const float* __restrict__ W,
    const float* __restrict__ bias1, const float* __restrict__ bias2,
    float* __restrict__ out)
{
    __shared__ unsigned AsH[2][128][9], AsL[2][128][9];
    __shared__ unsigned WsH[2][64][9],  WsL[2][64][9];

    const int tid  = threadIdx.x;
    const int lane = tid & 31;
    const int warp = tid >> 5;
    const int wr = warp >> 1, wc = warp & 1;
    const int m0 = blockIdx.x * 128;
    const int bb = m0 >> 9;
    const int tt0 = m0 & 511;
    const int n0 = blockIdx.y * 64;

    const int ar0 = tid >> 2, ac = tid & 3;
    const int wrow = tid >> 2;

    const float* Ar0 = A + (size_t)bb * sAb + (size_t)(tt0 + ar0) * sAt;
    const float* Ar1 = A + (size_t)bb * sAb + (size_t)(tt0 + ar0 + 64) * sAt;
    const float* Wr  = W + (size_t)(n0 + wrow) * K;

    const int nkt = K >> 4;

    float acc[2][4][4];
#pragma unroll
    for (int f = 0; f < 2; ++f)
#pragma unroll
        for (int n = 0; n < 4; ++n)
#pragma unroll
            for (int i = 0; i < 4; ++i) acc[f][n][i] = 0.f;

    float4 ra0 = *(const float4*)(Ar0 + ac * 4);
    float4 ra1 = *(const float4*)(Ar1 + ac * 4);
    float4 rw  = *(const float4*)(Wr  + ac * 4);
    {
        unsigned h0, h1, l0, l1;
        split4(ra0, h0, h1, l0, l1);
        AsH[0][ar0][2*ac] = h0; AsH[0][ar0][2*ac+1] = h1;
        AsL[0][ar0][2*ac] = l0; AsL[0][ar0][2*ac+1] = l1;
        split4(ra1, h0, h1, l0, l1);
        AsH[0][ar0+64][2*ac] = h0; AsH[0][ar0+64][2*ac+1] = h1;
        AsL[0][ar0+64][2*ac] = l0; AsL[0][ar0+64][2*ac+1] = l1;
        split4(rw, h0, h1, l0, l1);
        WsH[0][wrow][2*ac] = h0; WsH[0][wrow][2*ac+1] = h1;
        WsL[0][wrow][2*ac] = l0; WsL[0][wrow][2*ac+1] = l1;
    }
    __syncthreads();

    int cur = 0;
    for (int kt = 0; kt < nkt; ++kt) {
        const bool pf = (kt + 1 < nkt);
        if (pf) {
            const int k1 = (kt + 1) * 16;
            ra0 = *(const float4*)(Ar0 + k1 + ac * 4);
            ra1 = *(const float4*)(Ar1 + k1 + ac * 4);
            rw  = *(const float4*)(Wr  + k1 + ac * 4);
        }
        const int r = lane >> 2, c = lane & 3;
        unsigned ah[2][4], al[2][4], bh[4][2], bl[4][2];
#pragma unroll
        for (int f = 0; f < 2; ++f) {
            const int mb = wr * 32 + f * 16;
            ah[f][0] = AsH[cur][mb + r    ][c];
            ah[f][1] = AsH[cur][mb + r + 8][c];
            ah[f][2] = AsH[cur][mb + r    ][c + 4];
            ah[f][3] = AsH[cur][mb + r + 8][c + 4];
            al[f][0] = AsL[cur][mb + r    ][c];
            al[f][1] = AsL[cur][mb + r + 8][c];
            al[f][2] = AsL[cur][mb + r    ][c + 4];
            al[f][3] = AsL[cur][mb + r + 8][c + 4];
        }
#pragma unroll
        for (int n = 0; n < 4; ++n) {
            const int nb = wc * 32 + n * 8 + r;
            bh[n][0] = WsH[cur][nb][c];
            bh[n][1] = WsH[cur][nb][c + 4];
            bl[n][0] = WsL[cur][nb][c];
            bl[n][1] = WsL[cur][nb][c + 4];
        }
#pragma unroll
        for (int f = 0; f < 2; ++f)
#pragma unroll
            for (int n = 0; n < 4; ++n) {
                mma_bf16(acc[f][n], ah[f], bh[n]);
                mma_bf16(acc[f][n], ah[f], bl[n]);
                mma_bf16(acc[f][n], al[f], bh[n]);
            }
        if (pf) {
            const int nxt = cur ^ 1;
            unsigned h0, h1, l0, l1;
            split4(ra0, h0, h1, l0, l1);
            AsH[nxt][ar0][2*ac] = h0; AsH[nxt][ar0][2*ac+1] = h1;
            AsL[nxt][ar0][2*ac] = l0; AsL[nxt][ar0][2*ac+1] = l1;
            split4(ra1, h0, h1, l0, l1);
            AsH[nxt][ar0+64][2*ac] = h0; AsH[nxt][ar0+64][2*ac+1] = h1;
            AsL[nxt][ar0+64][2*ac] = l0; AsL[nxt][ar0+64][2*ac+1] = l1;
            split4(rw, h0, h1, l0, l1);
            WsH[nxt][wrow][2*ac] = h0; WsH[nxt][wrow][2*ac+1] = h1;
            WsL[nxt][wrow][2*ac] = l0; WsL[nxt][wrow][2*ac+1] = l1;
        }
        __syncthreads();
        cur ^= 1;
    }

    const int r = lane >> 2, c2 = (lane & 3) * 2;
#pragma unroll
    for (int f = 0; f < 2; ++f) {
#pragma unroll
        for (int n = 0; n < 4; ++n) {
            const int tloc = tt0 + wr * 32 + f * 16 + r;
            const int col = n0 + wc * 32 + n * 8 + c2;
            const float bb0 = bias1[col] + bias2[col];
            const float bb1 = bias1[col + 1] + bias2[col + 1];
            float* o0 = out + (size_t)tloc * 524288 + (size_t)bb * 2048 + col;
            o0[0]    = acc[f][n][0] + bb0;
            o0[1]    = acc[f][n][1] + bb1;
            float* o1 = out + (size_t)(tloc + 8) * 524288 + (size_t)bb * 2048 + col;
            o1[0]    = acc[f][n][2] + bb0;
            o1[1]    = acc[f][n][3] + bb1;
        }
    }
}

// ---------------------------------------------------------------------------
// lstm_persist_kernel v2: all 512 timesteps of one layer in one launch.
// 128 CTAs (1/SM), 256 threads (8 warps). CTA = 64 batch rows x 16 hidden
// units (64 gathered gate cols). W_hh tile SMEM-resident, loaded once (hi/lo
// bf16 split). Per step: K=512 processed in 2 chunks of 256; staging unpacks
// packed-bf16 h into swizzle-free padded SMEM (pure bit ops), then a 16-kt
// mma loop runs with NO barriers and NO conversions inside.
// Dynamic SMEM (u32 words): WsH[32*64*9]=18432, WsL=18432,
//   AsH[16*64*9]=9216, AsL=9216. Total 55296 words = 221,184 B.
// Gs (64x65 f32) aliases the A buffer (dead once accumulators are final).
// ---------------------------------------------------------------------------
#define WH(kt,row,cc) WsH[(kt)*576 + (row)*9 + (cc)]
#define WL(kt,row,cc) WsL[(kt)*576 + (row)*9 + (cc)]
#define AH(kt,row,cc) AsH[(kt)*576 + (row)*9 + (cc)]
#define AL(kt,row,cc) AsL[(kt)*576 + (row)*9 + (cc)]
#define PSMEM (55296 * 4)

__global__ void __launch_bounds__(256) lstm_persist_kernel(
    const unsigned* __restrict__ hp0,  // packed h_{-1} (zeros)
    const float* __restrict__ Whh,     // [2048, 512]
    const float* __restrict__ XP,      // [T,B,4H]
    float* __restrict__ Hbase,         // [T,B,H] fp32
    unsigned* __restrict__ HPbase,     // [T,B,H] packed
    float* __restrict__ cbuf,          // [B*H]
    unsigned* __restrict__ bar)
{
    extern __shared__ unsigned smem_u[];
    unsigned* WsH = smem_u;
    unsigned* WsL = WsH + 18432;
    unsigned* AsH = WsL + 18432;
    unsigned* AsL = AsH + 9216;
    float*    Gs  = (float*)AsH;       // alias: used only after all mma done

    const int tid  = threadIdx.x;
    const int lane = tid & 31;
    const int warp = tid >> 5;
    const int wr = warp >> 1, wc = warp & 1;
    const int m0 = (blockIdx.x & 3) * 64;    // batch base
    const int j0 = (blockIdx.x >> 2) * 16;   // hidden-unit base

    const int wl = tid >> 2;                              // local gate col 0..63
    const int ac = tid & 3;
    const int grow = ((wl >> 4) << 9) + j0 + (wl & 15);   // gate row in W_hh

    // --- load W tile into SMEM once (hi/lo split) ---
    {
        const float* Wr = Whh + (size_t)grow * 512;
        for (int kt = 0; kt < 32; ++kt) {
            float4 w = *(const float4*)(Wr + kt * 16 + ac * 4);
            unsigned h0w, h1w, l0w, l1w;
            split4(w, h0w, h1w, l0w, l1w);
            WH(kt, wl, 2*ac)   = h0w; WH(kt, wl, 2*ac+1) = h1w;
            WL(kt, wl, 2*ac)   = l0w; WL(kt, wl, 2*ac+1) = l1w;
        }
    }
    __syncthreads();

    const int r = lane >> 2, c = lane & 3;
    const int mb = wr * 16;
    const int arow = tid >> 2;                // staging row 0..63
    const int kbase = (tid & 3) * 4;          // staging k offset within chunk

    for (int t = 0; t < 512; ++t) {
        const unsigned* hp = t ? (HPbase + (size_t)(t - 1) * 131072) : hp0;
        const unsigned* src = hp + (size_t)(m0 + arow) * 512 + kbase;

        float acc[4][4];
#pragma unroll
        for (int n = 0; n < 4; ++n)
#pragma unroll
            for (int i = 0; i < 4; ++i) acc[n][i] = 0.f;

        for (int ch = 0; ch < 2; ++ch) {
            // --- stage chunk: 64 rows x 256 cols, unpack packed h ---
#pragma unroll
            for (int i = 0; i < 16; ++i) {
                const int k4 = kbase + i * 16;           // 0..252
                uint4 w4 = *(const uint4*)(src + ch * 256 + i * 16);
                const int kt2 = k4 >> 4;
                const int w0  = (k4 & 15) >> 1;          // 0,2,4,6
                const unsigned x0 = (w4.x & 0xFFFFu) | (w4.y << 16);
                const unsigned x1 = (w4.z & 0xFFFFu) | (w4.w << 16);
                const unsigned y0 = (w4.x >> 16) | (w4.y & 0xFFFF0000u);
                const unsigned y1 = (w4.z >> 16) | (w4.w & 0xFFFF0000u);
                AH(kt2, arow, w0) = x0; AH(kt2, arow, w0 + 1) = x1;
                AL(kt2, arow, w0) = y0; AL(kt2, arow, w0 + 1) = y1;
            }
            __syncthreads();

            // --- barrier-free mma loop over 16 k-tiles ---
#pragma unroll 4
            for (int kt2 = 0; kt2 < 16; ++kt2) {
                const int ktw = ch * 16 + kt2;
                unsigned ah[4], al[4], bh[4][2], bl[4][2];
                ah[0] = AH(kt2, mb + r,     c);
                ah[1] = AH(kt2, mb + r + 8, c);
                ah[2] = AH(kt2, mb + r,     c + 4);
                ah[3] = AH(kt2, mb + r + 8, c + 4);
                al[0] = AL(kt2, mb + r,     c);
                al[1] = AL(kt2, mb + r + 8, c);
                al[2] = AL(kt2, mb + r,     c + 4);
                al[3] = AL(kt2, mb + r + 8, c + 4);
#pragma unroll
                for (int n = 0; n < 4; ++n) {
                    const int nb = wc * 32 + n * 8 + r;
                    bh[n][0] = WH(ktw, nb, c);
                    bh[n][1] = WH(ktw, nb, c + 4);
                    bl[n][0] = WL(ktw, nb, c);
                    bl[n][1] = WL(ktw, nb, c + 4);
                }
#pragma unroll
                for (int n = 0; n < 4; ++n) {
                    mma_bf16(acc[n], ah, bh[n]);
                    mma_bf16(acc[n], ah, bl[n]);
                    mma_bf16(acc[n], al, bh[n]);
                }
            }
            __syncthreads();   // A buffer reusable (regs hold acc)
        }

        // --- stage gates into SMEM (Gs aliases A buffer; safe post-sync) ---
        {
            const int c2 = (lane & 3) * 2;
            const int rl = wr * 16 + r;
#pragma unroll
            for (int n = 0; n < 4; ++n) {
                const int cl = wc * 32 + n * 8 + c2;
                Gs[rl * 65 + cl]           = acc[n][0];
                Gs[rl * 65 + cl + 1]       = acc[n][1];
                Gs[(rl + 8) * 65 + cl]     = acc[n][2];
                Gs[(rl + 8) * 65 + cl + 1] = acc[n][3];
            }
        }
        __syncthreads();

        // --- gate nonlinearities + c/h update ---
        {
            const float* xpt = XP + (size_t)t * 524288;
            float* hout = Hbase + (size_t)t * 131072;
            unsigned* hpout = HPbase + (size_t)t * 131072;
            const int j  = tid & 15;
            const int mr = tid >> 4;
#pragma unroll
            for (int p = 0; p < 4; ++p) {
                const int m = mr + p * 16;
                const int b = m0 + m;
                const int jg = j0 + j;
                const float* xr = xpt + (size_t)b * 2048;
                const float xi = xr[jg]        + Gs[m * 65 + j];
                const float xf = xr[512 + jg]  + Gs[m * 65 + j + 16];
                const float xg = xr[1024 + jg] + Gs[m * 65 + j + 32];
                const float xo = xr[1536 + jg] + Gs[m * 65 + j + 48];
                const float ig = sigf(xi), fg = sigf(xf), gg = tanhf_(xg), og = sigf(xo);
                const size_t ci = (size_t)b * 512 + jg;
                const float cv = fg * cbuf[ci] + ig * gg;
                cbuf[ci] = cv;
                const float h = og * tanhf_(cv);
                hout[(size_t)b * 512 + jg] = h;
                const __nv_bfloat16 hh = __float2bfloat16(h);
                hpout[(size_t)b * 512 + jg] =
                    pack2(hh, __float2bfloat16(h - __bfloat162float(hh)));
            }
        }

        // --- grid-wide barrier (monotonic counter; reset before launch) ---
        __threadfence();
        __syncthreads();
        if (tid == 0) {
            atomicAdd(bar, 1u);
            const unsigned target = 128u * (unsigned)(t + 1);
            while (*(volatile unsigned*)bar < target) { }
        }
        __syncthreads();
    }
}

// ---------------------------------------------------------------------------
__global__ void zero_kernel(float* __restrict__ p, int n, unsigned* __restrict__ bar) {
    const int i = blockIdx.x * 256 + threadIdx.x;
    if (i < n) p[i] = 0.f;
    if (i == 0) *bar = 0u;
}

__global__ void final_kernel(
    const float* __restrict__ hlast,
    const float* __restrict__ Wl, const float* __restrict__ bl,
    float* __restrict__ y)
{
    const int b = blockIdx.x * 8 + (threadIdx.x >> 5);
    const int lane = threadIdx.x & 31;
    const float* hr = hlast + (size_t)b * 512;
    float s = 0.f;
    for (int k = lane; k < 512; k += 32) s += hr[k] * Wl[k];
#pragma unroll
    for (int o = 16; o; o >>= 1) s += __shfl_xor_sync(0xffffffffu, s, o);
    if (lane == 0) y[b] = s + bl[0];
}

// ---------------------------------------------------------------------------
extern "C" void kernel_launch(void* const* d_in, const int* in_sizes, int n_in,
                              void* d_out, int out_size)
{
    const float* X     = (const float*)d_in[0];
    const float* W_ih0 = (const float*)d_in[1];
    const float* W_hh0 = (const float*)d_in[2];
    const float* b_ih0 = (const float*)d_in[3];
    const float* b_hh0 = (const float*)d_in[4];
    const float* W_ih1 = (const float*)d_in[5];
    const float* W_hh1 = (const float*)d_in[6];
    const float* b_ih1 = (const float*)d_in[7];
    const float* b_hh1 = (const float*)d_in[8];
    const float* W_lin = (const float*)d_in[9];
    const float* b_lin = (const float*)d_in[10];
    float* y = (float*)d_out;

    float *XP, *Hb, *Cb, *Zb;
    unsigned *HPb, *bar;
    cudaGetSymbolAddress((void**)&XP, g_XP);
    cudaGetSymbolAddress((void**)&Hb, g_H);
    cudaGetSymbolAddress((void**)&HPb, g_HP);
    cudaGetSymbolAddress((void**)&Cb, g_C);
    cudaGetSymbolAddress((void**)&Zb, g_Z);
    cudaGetSymbolAddress((void**)&bar, g_bar);

    static bool attr_done = false;
    if (!attr_done) {
        cudaFuncSetAttribute(lstm_persist_kernel,
                             cudaFuncAttributeMaxDynamicSharedMemorySize, PSMEM);
        attr_done = true;
    }

    // Layer 0
    zero_kernel<<<512, 256>>>(Cb, 256 * 512, bar);
    proj_kernel<<<dim3(1024, 32), 256>>>(X, 131072, 256, 256, W_ih0, b_ih0, b_hh0, XP);
    lstm_persist_kernel<<<128, 256, PSMEM>>>((const unsigned*)Zb, W_hh0, XP, Hb, HPb, Cb, bar);

    // Layer 1
    proj_kernel<<<dim3(1024, 32), 256>>>(Hb, 512, 131072, 512, W_ih1, b_ih1, b_hh1, XP);
    zero_kernel<<<512, 256>>>(Cb, 256 * 512, bar);
    lstm_persist_kernel<<<128, 256, PSMEM>>>((const unsigned*)Zb, W_hh1, XP, Hb, HPb, Cb, bar);

    final_kernel<<<32, 256>>>(Hb + (size_t)511 * 131072, W_lin, b_lin, y);
}

// round 10
// speedup vs baseline: 1.4070x; 1.3547x over previous
#include <cuda_runtime.h>
#include <cuda_fp16.h>
#include <cstdint>
#include <cstddef>

// Problem sizes: B=256, T=512, I=256, H=512, 4H=2048
// Layouts: g_XP [T,B,4H] fp32, g_H [T,B,H] fp32, g_HP [T,B,H] fp16 (half2 packed)

__device__ float    g_XP[(size_t)512 * 256 * 2048]; // 1 GiB input projections
__device__ float    g_H [(size_t)512 * 256 * 512];  // fp32 hidden states
__device__ unsigned g_HP[(size_t)512 * 256 * 256];  // fp16 hidden states (2/u32)
__device__ float    g_C [256 * 512];                // cell state
__device__ float    g_Z [256 * 512];                // zeros (h_{-1}; any view)
__device__ unsigned g_bar;                          // grid barrier counter

__device__ __forceinline__ unsigned pack2h(__half a, __half b) {
    __half2 t = __halves2half2(a, b);
    return *reinterpret_cast<unsigned*>(&t);
}
__device__ __forceinline__ unsigned r2h(float a, float b) {
    __half2 t = __floats2half2_rn(a, b);
    return *reinterpret_cast<unsigned*>(&t);
}

// Split float4 into hi/lo fp16x2 words (k-even in low half).
__device__ __forceinline__ void split4h(float4 v, unsigned& h0, unsigned& h1,
                                        unsigned& l0, unsigned& l1) {
    __half hx = __float2half(v.x), hy = __float2half(v.y);
    __half hz = __float2half(v.z), hw = __float2half(v.w);
    h0 = pack2h(hx, hy);
    h1 = pack2h(hz, hw);
    l0 = r2h(v.x - __half2float(hx), v.y - __half2float(hy));
    l1 = r2h(v.z - __half2float(hz), v.w - __half2float(hw));
}

__device__ __forceinline__ void mma_f16(float* d, const unsigned* a, const unsigned* b) {
    asm volatile(
        "mma.sync.aligned.m16n8k16.row.col.f32.f16.f16.f32 "
        "{%0,%1,%2,%3}, {%4,%5,%6,%7}, {%8,%9}, {%0,%1,%2,%3};\n"
        : "+f"(d[0]), "+f"(d[1]), "+f"(d[2]), "+f"(d[3])
        : "r"(a[0]), "r"(a[1]), "r"(a[2]), "r"(a[3]), "r"(b[0]), "r"(b[1]));
}

__device__ __forceinline__ float sigf(float x)   { return 1.f / (1.f + __expf(-x)); }
__device__ __forceinline__ float tanhf_(float x) { return 2.f / (1.f + __expf(-2.f * x)) - 1.f; }

// ---------------------------------------------------------------------------
// proj_kernel: out[t,b,0:2048] = A_row(b,t)[0:K] @ W[2048,K]^T + bias1 + bias2
// fp16 2-term: acc += Ah*Whi + Ah*Wlo. A single-rounded fp16.
// CTA 128m x 64n, BK=16, 8 warps (4x2), warp tile 32m x 32n.
// ---------------------------------------------------------------------------
__global__ void __launch_bounds__(256) proj_kernel(
    const float* __restrict__ A, int sAb, int sAt, int K,
    const float* __restrict__ W,
    const float* __restrict__ bias1, const float* __restrict__ bias2,
    float* __restrict__ out)
{
    __shared__ unsigned As [2][128][9];
    __shared__ unsigned WsH[2][64][9], WsL[2][64][9];

    const int tid  = threadIdx.x;
    const int lane = tid & 31;
    const int warp = tid >> 5;
    const int wr = warp >> 1, wc = warp & 1;
    const int m0 = blockIdx.x * 128;
    const int bb = m0 >> 9;
    const int tt0 = m0 & 511;
    const int n0 = blockIdx.y * 64;

    const int ar0 = tid >> 2, ac = tid & 3;
    const int wrow = tid >> 2;

    const float* Ar0 = A + (size_t)bb * sAb + (size_t)(tt0 + ar0) * sAt;
    const float* Ar1 = A + (size_t)bb * sAb + (size_t)(tt0 + ar0 + 64) * sAt;
    const float* Wr  = W + (size_t)(n0 + wrow) * K;

    const int nkt = K >> 4;

    float acc[2][4][4];
#pragma unroll
    for (int f = 0; f < 2; ++f)
#pragma unroll
        for (int n = 0; n < 4; ++n)
#pragma unroll
            for (int i = 0; i < 4; ++i) acc[f][n][i] = 0.f;

    float4 ra0 = *(const float4*)(Ar0 + ac * 4);
    float4 ra1 = *(const float4*)(Ar1 + ac * 4);
    float4 rw  = *(const float4*)(Wr  + ac * 4);
    {
        As[0][ar0][2*ac]      = r2h(ra0.x, ra0.y);
        As[0][ar0][2*ac+1]    = r2h(ra0.z, ra0.w);
        As[0][ar0+64][2*ac]   = r2h(ra1.x, ra1.y);
        As[0][ar0+64][2*ac+1] = r2h(ra1.z, ra1.w);
        unsigned h0, h1, l0, l1;
        split4h(rw, h0, h1, l0, l1);
        WsH[0][wrow][2*ac] = h0; WsH[0][wrow][2*ac+1] = h1;
        WsL[0][wrow][2*ac] = l0; WsL[0][wrow][2*ac+1] = l1;
    }
    __syncthreads();

    int cur = 0;
    for (int kt = 0; kt < nkt; ++kt) {
        const bool pf = (kt + 1 < nkt);
        if (pf) {
            const int k1 = (kt + 1) * 16;
            ra0 = *(const float4*)(Ar0 + k1 + ac * 4);
            ra1 = *(const float4*)(Ar1 + k1 + ac * 4);
            rw  = *(const float4*)(Wr  + k1 + ac * 4);
        }
        const int r = lane >> 2, c = lane & 3;
        unsigned ah[2][4], bh[4][2], bl[4][2];
#pragma unroll
        for (int f = 0; f < 2; ++f) {
            const int mb = wr * 32 + f * 16;
            ah[f][0] = As[cur][mb + r    ][c];
            ah[f][1] = As[cur][mb + r + 8][c];
            ah[f][2] = As[cur][mb + r    ][c + 4];
            ah[f][3] = As[cur][mb + r + 8][c + 4];
        }
#pragma unroll
        for (int n = 0; n < 4; ++n) {
            const int nb = wc * 32 + n * 8 + r;
            bh[n][0] = WsH[cur][nb][c];
            bh[n][1] = WsH[cur][nb][c + 4];
            bl[n][0] = WsL[cur][nb][c];
            bl[n][1] = WsL[cur][nb][c + 4];
        }
#pragma unroll
        for (int f = 0; f < 2; ++f)
#pragma unroll
            for (int n = 0; n < 4; ++n) {
                mma_f16(acc[f][n], ah[f], bh[n]);
                mma_f16(acc[f][n], ah[f], bl[n]);
            }
        if (pf) {
            const int nxt = cur ^ 1;
            As[nxt][ar0][2*ac]      = r2h(ra0.x, ra0.y);
            As[nxt][ar0][2*ac+1]    = r2h(ra0.z, ra0.w);
            As[nxt][ar0+64][2*ac]   = r2h(ra1.x, ra1.y);
            As[nxt][ar0+64][2*ac+1] = r2h(ra1.z, ra1.w);
            unsigned h0, h1, l0, l1;
            split4h(rw, h0, h1, l0, l1);
            WsH[nxt][wrow][2*ac] = h0; WsH[nxt][wrow][2*ac+1] = h1;
            WsL[nxt][wrow][2*ac] = l0; WsL[nxt][wrow][2*ac+1] = l1;
        }
        __syncthreads();
        cur ^= 1;
    }

    const int r = lane >> 2, c2 = (lane & 3) * 2;
#pragma unroll
    for (int f = 0; f < 2; ++f) {
#pragma unroll
        for (int n = 0; n < 4; ++n) {
            const int tloc = tt0 + wr * 32 + f * 16 + r;
            const int col = n0 + wc * 32 + n * 8 + c2;
            const float bb0 = bias1[col] + bias2[col];
            const float bb1 = bias1[col + 1] + bias2[col + 1];
            float* o0 = out + (size_t)tloc * 524288 + (size_t)bb * 2048 + col;
            o0[0]    = acc[f][n][0] + bb0;
            o0[1]    = acc[f][n][1] + bb1;
            float* o1 = out + (size_t)(tloc + 8) * 524288 + (size_t)bb * 2048 + col;
            o1[0]    = acc[f][n][2] + bb0;
            o1[1]    = acc[f][n][3] + bb1;
        }
    }
}

// ---------------------------------------------------------------------------
// lstm_persist_kernel v3: all 512 timesteps of one layer in one launch.
// 128 CTAs (1/SM), 256 threads (8 warps as 2m x 4n, warp tile 32m x 16n).
// CTA = 64 batch rows x 16 hidden units (64 gathered gate cols).
// fp16 2-term: acc += Ah*Whi + Ah*Wlo; h stored as fp16 -> staging is a pure
// uint4 copy. W_hh tile SMEM-resident (hi/lo fp16), loaded once.
// Dynamic SMEM (u32): WsH 18432 + WsL 18432 + As 9216 = 46080 w = 184,320 B.
// Gs (64x65 f32) aliases As.
// ---------------------------------------------------------------------------
#define WH(kt,row,cc) WsH[(kt)*576 + (row)*9 + (cc)]
#define WL(kt,row,cc) WsL[(kt)*576 + (row)*9 + (cc)]
#define AH(kt,row,cc) As [(kt)*576 + (row)*9 + (cc)]
#define PSMEM (46080 * 4)

__global__ void __launch_bounds__(256) lstm_persist_kernel(
    const unsigned* __restrict__ hp0,  // fp16 h_{-1} (zeros), row = 256 u32
    const float* __restrict__ Whh,     // [2048, 512]
    const float* __restrict__ XP,      // [T,B,4H]
    float* __restrict__ Hbase,         // [T,B,H] fp32
    unsigned* __restrict__ HPbase,     // [T,B,H] fp16, t-slab = 65536 u32
    float* __restrict__ cbuf,          // [B*H]
    unsigned* __restrict__ bar)
{
    extern __shared__ unsigned smem_u[];
    unsigned* WsH = smem_u;
    unsigned* WsL = WsH + 18432;
    unsigned* As  = WsL + 18432;
    float*    Gs  = (float*)As;        // alias: used only after all mma done

    const int tid  = threadIdx.x;
    const int lane = tid & 31;
    const int warp = tid >> 5;
    const int mbw = (warp >> 2) * 32;        // warp m base (0/32)
    const int nb0 = (warp & 3) * 16;         // warp n base (0..48)
    const int m0 = (blockIdx.x & 3) * 64;    // batch base
    const int j0 = (blockIdx.x >> 2) * 16;   // hidden-unit base

    const int wl = tid >> 2;                              // local gate col 0..63
    const int ac = tid & 3;
    const int grow = ((wl >> 4) << 9) + j0 + (wl & 15);   // gate row in W_hh

    // --- load W tile into SMEM once (fp16 hi/lo split) ---
    {
        const float* Wr = Whh + (size_t)grow * 512;
        for (int kt = 0; kt < 32; ++kt) {
            float4 w = *(const float4*)(Wr + kt * 16 + ac * 4);
            unsigned h0w, h1w, l0w, l1w;
            split4h(w, h0w, h1w, l0w, l1w);
            WH(kt, wl, 2*ac)   = h0w; WH(kt, wl, 2*ac+1) = h1w;
            WL(kt, wl, 2*ac)   = l0w; WL(kt, wl, 2*ac+1) = l1w;
        }
    }
    __syncthreads();

    const int r = lane >> 2, c = lane & 3;
    const int arow = tid >> 2;                // staging row 0..63
    const int kw = (tid & 3) * 4;             // staging u32-word base

    for (int t = 0; t < 512; ++t) {
        const unsigned* hp = t ? (HPbase + (size_t)(t - 1) * 65536) : hp0;
        const unsigned* src = hp + (size_t)(m0 + arow) * 256 + kw;

        float acc[2][2][4];
#pragma unroll
        for (int mf = 0; mf < 2; ++mf)
#pragma unroll
            for (int nf = 0; nf < 2; ++nf)
#pragma unroll
                for (int i = 0; i < 4; ++i) acc[mf][nf][i] = 0.f;

        for (int ch = 0; ch < 2; ++ch) {
            // --- stage chunk: 64 rows x 128 u32 (fp16 pairs) — pure copy ---
#pragma unroll
            for (int i = 0; i < 8; ++i) {
                const int w = kw + i * 16;               // 0..124, mult of 4
                uint4 v = *(const uint4*)(src + ch * 128 + i * 16);
                const int kt2 = w >> 3;
                const int wq  = w & 7;                   // 0 or 4
                AH(kt2, arow, wq)     = v.x;
                AH(kt2, arow, wq + 1) = v.y;
                AH(kt2, arow, wq + 2) = v.z;
                AH(kt2, arow, wq + 3) = v.w;
            }
            __syncthreads();

            // --- barrier-free mma loop over 16 k-tiles ---
#pragma unroll 4
            for (int kt2 = 0; kt2 < 16; ++kt2) {
                const int ktw = ch * 16 + kt2;
                unsigned ah[2][4], bh[2][2], bl[2][2];
#pragma unroll
                for (int mf = 0; mf < 2; ++mf) {
                    const int mm = mbw + mf * 16;
                    ah[mf][0] = AH(kt2, mm + r,     c);
                    ah[mf][1] = AH(kt2, mm + r + 8, c);
                    ah[mf][2] = AH(kt2, mm + r,     c + 4);
                    ah[mf][3] = AH(kt2, mm + r + 8, c + 4);
                }
#pragma unroll
                for (int nf = 0; nf < 2; ++nf) {
                    const int nn = nb0 + nf * 8 + r;
                    bh[nf][0] = WH(ktw, nn, c);
                    bh[nf][1] = WH(ktw, nn, c + 4);
                    bl[nf][0] = WL(ktw, nn, c);
                    bl[nf][1] = WL(ktw, nn, c + 4);
                }
#pragma unroll
                for (int mf = 0; mf < 2; ++mf)
#pragma unroll
                    for (int nf = 0; nf < 2; ++nf) {
                        mma_f16(acc[mf][nf], ah[mf], bh[nf]);
                        mma_f16(acc[mf][nf], ah[mf], bl[nf]);
                    }
            }
            __syncthreads();   // A buffer reusable (regs hold acc)
        }

        // --- stage gates into SMEM (Gs aliases A buffer; safe post-sync) ---
        {
            const int c2 = (lane & 3) * 2;
#pragma unroll
            for (int mf = 0; mf < 2; ++mf)
#pragma unroll
                for (int nf = 0; nf < 2; ++nf) {
                    const int rl = mbw + mf * 16 + r;
                    const int cl = nb0 + nf * 8 + c2;
                    Gs[rl * 65 + cl]           = acc[mf][nf][0];
                    Gs[rl * 65 + cl + 1]       = acc[mf][nf][1];
                    Gs[(rl + 8) * 65 + cl]     = acc[mf][nf][2];
                    Gs[(rl + 8) * 65 + cl + 1] = acc[mf][nf][3];
                }
        }
        __syncthreads();

        // --- gate nonlinearities + c/h update (2 adjacent j per thread) ---
        {
            const float* xpt = XP + (size_t)t * 524288;
            float* hout = Hbase + (size_t)t * 131072;
            unsigned* hpout = HPbase + (size_t)t * 65536;
            const int j2 = (tid & 7) * 2;
            const int mr = tid >> 3;            // 0..31
#pragma unroll
            for (int p = 0; p < 2; ++p) {
                const int m = mr + p * 32;
                const int b = m0 + m;
                const int jg = j0 + j2;
                const float* xr = xpt + (size_t)b * 2048;
                const float2 xi = *(const float2*)(xr + jg);
                const float2 xf = *(const float2*)(xr + 512 + jg);
                const float2 xg = *(const float2*)(xr + 1024 + jg);
                const float2 xo = *(const float2*)(xr + 1536 + jg);
                float* cp = cbuf + (size_t)b * 512 + jg;
                const float2 cc = *(const float2*)cp;
                const float* gr = Gs + m * 65 + j2;

                const float i0 = sigf(xi.x + gr[0]);
                const float i1 = sigf(xi.y + gr[1]);
                const float f0 = sigf(xf.x + gr[16]);
                const float f1 = sigf(xf.y + gr[17]);
                const float g0 = tanhf_(xg.x + gr[32]);
                const float g1 = tanhf_(xg.y + gr[33]);
                const float o0 = sigf(xo.x + gr[48]);
                const float o1 = sigf(xo.y + gr[49]);
                const float c0 = f0 * cc.x + i0 * g0;
                const float c1 = f1 * cc.y + i1 * g1;
                *(float2*)cp = make_float2(c0, c1);
                const float h0 = o0 * tanhf_(c0);
                const float h1 = o1 * tanhf_(c1);
                *(float2*)(hout + (size_t)b * 512 + jg) = make_float2(h0, h1);
                hpout[(size_t)b * 256 + (jg >> 1)] = r2h(h0, h1);
            }
        }

        // --- grid-wide barrier (monotonic counter; reset before launch) ---
        __threadfence();
        __syncthreads();
        if (tid == 0) {
            atomicAdd(bar, 1u);
            const unsigned target = 128u * (unsigned)(t + 1);
            while (*(volatile unsigned*)bar < target) { }
        }
        __syncthreads();
    }
}

// ---------------------------------------------------------------------------
__global__ void zero_kernel(float* __restrict__ p, int n, unsigned* __restrict__ bar) {
    const int i = blockIdx.x * 256 + threadIdx.x;
    if (i < n) p[i] = 0.f;
    if (i == 0) *bar = 0u;
}

__global__ void final_kernel(
    const float* __restrict__ hlast,
    const float* __restrict__ Wl, const float* __restrict__ bl,
    float* __restrict__ y)
{
    const int b = blockIdx.x * 8 + (threadIdx.x >> 5);
    const int lane = threadIdx.x & 31;
    const float* hr = hlast + (size_t)b * 512;
    float s = 0.f;
    for (int k = lane; k < 512; k += 32) s += hr[k] * Wl[k];
#pragma unroll
    for (int o = 16; o; o >>= 1) s += __shfl_xor_sync(0xffffffffu, s, o);
    if (lane == 0) y[b] = s + bl[0];
}

// ---------------------------------------------------------------------------
extern "C" void kernel_launch(void* const* d_in, const int* in_sizes, int n_in,
                              void* d_out, int out_size)
{
    const float* X     = (const float*)d_in[0];
    const float* W_ih0 = (const float*)d_in[1];
    const float* W_hh0 = (const float*)d_in[2];
    const float* b_ih0 = (const float*)d_in[3];
    const float* b_hh0 = (const float*)d_in[4];
    const float* W_ih1 = (const float*)d_in[5];
    const float* W_hh1 = (const float*)d_in[6];
    const float* b_ih1 = (const float*)d_in[7];
    const float* b_hh1 = (const float*)d_in[8];
    const float* W_lin = (const float*)d_in[9];
    const float* b_lin = (const float*)d_in[10];
    float* y = (float*)d_out;

    float *XP, *Hb, *Cb, *Zb;
    unsigned *HPb, *bar;
    cudaGetSymbolAddress((void**)&XP, g_XP);
    cudaGetSymbolAddress((void**)&Hb, g_H);
    cudaGetSymbolAddress((void**)&HPb, g_HP);
    cudaGetSymbolAddress((void**)&Cb, g_C);
    cudaGetSymbolAddress((void**)&Zb, g_Z);
    cudaGetSymbolAddress((void**)&bar, g_bar);

    static bool attr_done = false;
    if (!attr_done) {
        cudaFuncSetAttribute(lstm_persist_kernel,
                             cudaFuncAttributeMaxDynamicSharedMemorySize, PSMEM);
        attr_done = true;
    }

    // Layer 0
    zero_kernel<<<512, 256>>>(Cb, 256 * 512, bar);
    proj_kernel<<<dim3(1024, 32), 256>>>(X, 131072, 256, 256, W_ih0, b_ih0, b_hh0, XP);
    lstm_persist_kernel<<<128, 256, PSMEM>>>((const unsigned*)Zb, W_hh0, XP, Hb, HPb, Cb, bar);

    // Layer 1
    proj_kernel<<<dim3(1024, 32), 256>>>(Hb, 512, 131072, 512, W_ih1, b_ih1, b_hh1, XP);
    zero_kernel<<<512, 256>>>(Cb, 256 * 512, bar);
    lstm_persist_kernel<<<128, 256, PSMEM>>>((const unsigned*)Zb, W_hh1, XP, Hb, HPb, Cb, bar);

    final_kernel<<<32, 256>>>(Hb + (size_t)511 * 131072, W_lin, b_lin, y);
}

// round 11
// speedup vs baseline: 1.5878x; 1.1285x over previous
#include <cuda_runtime.h>
#include <cuda_fp16.h>
#include <cstdint>
#include <cstddef>

// Problem sizes: B=256, T=512, I=256, H=512, 4H=2048
// Layouts: g_XP [T,B,4H] fp32, g_H [T,B,H] fp32, g_HP [T,B,H] fp16 (half2 packed)

__device__ float    g_XP[(size_t)512 * 256 * 2048]; // 1 GiB input projections
__device__ float    g_H [(size_t)512 * 256 * 512];  // fp32 hidden states
__device__ unsigned g_HP[(size_t)512 * 256 * 256];  // fp16 hidden states (2/u32)
__device__ float    g_C [256 * 512];                // cell state
__device__ float    g_Z [256 * 512];                // zeros (h_{-1}; any view)
__device__ unsigned g_bar;                          // grid barrier counter

__device__ __forceinline__ unsigned pack2h(__half a, __half b) {
    __half2 t = __halves2half2(a, b);
    return *reinterpret_cast<unsigned*>(&t);
}
__device__ __forceinline__ unsigned r2h(float a, float b) {
    __half2 t = __floats2half2_rn(a, b);
    return *reinterpret_cast<unsigned*>(&t);
}

// Split float4 into hi/lo fp16x2 words (k-even in low half).
__device__ __forceinline__ void split4h(float4 v, unsigned& h0, unsigned& h1,
                                        unsigned& l0, unsigned& l1) {
    __half hx = __float2half(v.x), hy = __float2half(v.y);
    __half hz = __float2half(v.z), hw = __float2half(v.w);
    h0 = pack2h(hx, hy);
    h1 = pack2h(hz, hw);
    l0 = r2h(v.x - __half2float(hx), v.y - __half2float(hy));
    l1 = r2h(v.z - __half2float(hz), v.w - __half2float(hw));
}

__device__ __forceinline__ void mma_f16(float* d, const unsigned* a, const unsigned* b) {
    asm volatile(
        "mma.sync.aligned.m16n8k16.row.col.f32.f16.f16.f32 "
        "{%0,%1,%2,%3}, {%4,%5,%6,%7}, {%8,%9}, {%0,%1,%2,%3};\n"
        : "+f"(d[0]), "+f"(d[1]), "+f"(d[2]), "+f"(d[3])
        : "r"(a[0]), "r"(a[1]), "r"(a[2]), "r"(a[3]), "r"(b[0]), "r"(b[1]));
}

__device__ __forceinline__ float sigf(float x)   { return 1.f / (1.f + __expf(-x)); }
__device__ __forceinline__ float tanhf_(float x) { return 2.f / (1.f + __expf(-2.f * x)) - 1.f; }

// ---------------------------------------------------------------------------
// proj_kernel: out[t,b,0:2048] = A_row(b,t)[0:K] @ W[2048,K]^T + bias1 + bias2
// fp16 2-term (W split hi/lo; A single-rounded). Unchanged from R10 (validated).
// ---------------------------------------------------------------------------
__global__ void __launch_bounds__(256) proj_kernel(
    const float* __restrict__ A, int sAb, int sAt, int K,
    const float* __restrict__ W,
    const float* __restrict__ bias1, const float* __restrict__ bias2,
    float* __restrict__ out)
{
    __shared__ unsigned As [2][128][9];
    __shared__ unsigned WsH[2][64][9], WsL[2][64][9];

    const int tid  = threadIdx.x;
    const int lane = tid & 31;
    const int warp = tid >> 5;
    const int wr = warp >> 1, wc = warp & 1;
    const int m0 = blockIdx.x * 128;
    const int bb = m0 >> 9;
    const int tt0 = m0 & 511;
    const int n0 = blockIdx.y * 64;

    const int ar0 = tid >> 2, ac = tid & 3;
    const int wrow = tid >> 2;

    const float* Ar0 = A + (size_t)bb * sAb + (size_t)(tt0 + ar0) * sAt;
    const float* Ar1 = A + (size_t)bb * sAb + (size_t)(tt0 + ar0 + 64) * sAt;
    const float* Wr  = W + (size_t)(n0 + wrow) * K;

    const int nkt = K >> 4;

    float acc[2][4][4];
#pragma unroll
    for (int f = 0; f < 2; ++f)
#pragma unroll
        for (int n = 0; n < 4; ++n)
#pragma unroll
            for (int i = 0; i < 4; ++i) acc[f][n][i] = 0.f;

    float4 ra0 = *(const float4*)(Ar0 + ac * 4);
    float4 ra1 = *(const float4*)(Ar1 + ac * 4);
    float4 rw  = *(const float4*)(Wr  + ac * 4);
    {
        As[0][ar0][2*ac]      = r2h(ra0.x, ra0.y);
        As[0][ar0][2*ac+1]    = r2h(ra0.z, ra0.w);
        As[0][ar0+64][2*ac]   = r2h(ra1.x, ra1.y);
        As[0][ar0+64][2*ac+1] = r2h(ra1.z, ra1.w);
        unsigned h0, h1, l0, l1;
        split4h(rw, h0, h1, l0, l1);
        WsH[0][wrow][2*ac] = h0; WsH[0][wrow][2*ac+1] = h1;
        WsL[0][wrow][2*ac] = l0; WsL[0][wrow][2*ac+1] = l1;
    }
    __syncthreads();

    int cur = 0;
    for (int kt = 0; kt < nkt; ++kt) {
        const bool pf = (kt + 1 < nkt);
        if (pf) {
            const int k1 = (kt + 1) * 16;
            ra0 = *(const float4*)(Ar0 + k1 + ac * 4);
            ra1 = *(const float4*)(Ar1 + k1 + ac * 4);
            rw  = *(const float4*)(Wr  + k1 + ac * 4);
        }
        const int r = lane >> 2, c = lane & 3;
        unsigned ah[2][4], bh[4][2], bl[4][2];
#pragma unroll
        for (int f = 0; f < 2; ++f) {
            const int mb = wr * 32 + f * 16;
            ah[f][0] = As[cur][mb + r    ][c];
            ah[f][1] = As[cur][mb + r + 8][c];
            ah[f][2] = As[cur][mb + r    ][c + 4];
            ah[f][3] = As[cur][mb + r + 8][c + 4];
        }
#pragma unroll
        for (int n = 0; n < 4; ++n) {
            const int nb = wc * 32 + n * 8 + r;
            bh[n][0] = WsH[cur][nb][c];
            bh[n][1] = WsH[cur][nb][c + 4];
            bl[n][0] = WsL[cur][nb][c];
            bl[n][1] = WsL[cur][nb][c + 4];
        }
#pragma unroll
        for (int f = 0; f < 2; ++f)
#pragma unroll
            for (int n = 0; n < 4; ++n) {
                mma_f16(acc[f][n], ah[f], bh[n]);
                mma_f16(acc[f][n], ah[f], bl[n]);
            }
        if (pf) {
            const int nxt = cur ^ 1;
            As[nxt][ar0][2*ac]      = r2h(ra0.x, ra0.y);
            As[nxt][ar0][2*ac+1]    = r2h(ra0.z, ra0.w);
            As[nxt][ar0+64][2*ac]   = r2h(ra1.x, ra1.y);
            As[nxt][ar0+64][2*ac+1] = r2h(ra1.z, ra1.w);
            unsigned h0, h1, l0, l1;
            split4h(rw, h0, h1, l0, l1);
            WsH[nxt][wrow][2*ac] = h0; WsH[nxt][wrow][2*ac+1] = h1;
            WsL[nxt][wrow][2*ac] = l0; WsL[nxt][wrow][2*ac+1] = l1;
        }
        __syncthreads();
        cur ^= 1;
    }

    const int r = lane >> 2, c2 = (lane & 3) * 2;
#pragma unroll
    for (int f = 0; f < 2; ++f) {
#pragma unroll
        for (int n = 0; n < 4; ++n) {
            const int tloc = tt0 + wr * 32 + f * 16 + r;
            const int col = n0 + wc * 32 + n * 8 + c2;
            const float bb0 = bias1[col] + bias2[col];
            const float bb1 = bias1[col + 1] + bias2[col + 1];
            float* o0 = out + (size_t)tloc * 524288 + (size_t)bb * 2048 + col;
            o0[0]    = acc[f][n][0] + bb0;
            o0[1]    = acc[f][n][1] + bb1;
            float* o1 = out + (size_t)(tloc + 8) * 524288 + (size_t)bb * 2048 + col;
            o1[0]    = acc[f][n][2] + bb0;
            o1[1]    = acc[f][n][3] + bb1;
        }
    }
}

// ---------------------------------------------------------------------------
// lstm_persist_kernel v4: all 512 timesteps of one layer in one launch.
// 128 CTAs (1/SM), 256 threads (8 warps as 2m x 4n, warp tile 32m x 16n).
// CTA = 64 batch rows x 16 hidden units (64 gathered gate cols).
// SINGLE-term fp16: acc += Ah*Wh (both single-rounded fp16).
// h stored fp16 -> staging is a pure uint4 copy; chunk-1 loads are
// prefetched into registers during chunk-0's mma loop.
// Dynamic SMEM (u32): WsH 18432 + As 9216 = 27648 w = 110,592 B.
// Gs (64x65 f32) aliases As.
// ---------------------------------------------------------------------------
#define WH(kt,row,cc) WsH[(kt)*576 + (row)*9 + (cc)]
#define AH(kt,row,cc) As [(kt)*576 + (row)*9 + (cc)]
#define PSMEM (27648 * 4)

__global__ void __launch_bounds__(256) lstm_persist_kernel(
    const unsigned* __restrict__ hp0,  // fp16 h_{-1} (zeros), row = 256 u32
    const float* __restrict__ Whh,     // [2048, 512]
    const float* __restrict__ XP,      // [T,B,4H]
    float* __restrict__ Hbase,         // [T,B,H] fp32
    unsigned* __restrict__ HPbase,     // [T,B,H] fp16, t-slab = 65536 u32
    float* __restrict__ cbuf,          // [B*H]
    unsigned* __restrict__ bar)
{
    extern __shared__ unsigned smem_u[];
    unsigned* WsH = smem_u;
    unsigned* As  = WsH + 18432;
    float*    Gs  = (float*)As;        // alias: used only after all mma done

    const int tid  = threadIdx.x;
    const int lane = tid & 31;
    const int warp = tid >> 5;
    const int mbw = (warp >> 2) * 32;        // warp m base (0/32)
    const int nb0 = (warp & 3) * 16;         // warp n base (0..48)
    const int m0 = (blockIdx.x & 3) * 64;    // batch base
    const int j0 = (blockIdx.x >> 2) * 16;   // hidden-unit base

    const int wl = tid >> 2;                              // local gate col 0..63
    const int ac = tid & 3;
    const int grow = ((wl >> 4) << 9) + j0 + (wl & 15);   // gate row in W_hh

    // --- load W tile into SMEM once (single-rounded fp16) ---
    {
        const float* Wr = Whh + (size_t)grow * 512;
        for (int kt = 0; kt < 32; ++kt) {
            float4 w = *(const float4*)(Wr + kt * 16 + ac * 4);
            WH(kt, wl, 2*ac)   = r2h(w.x, w.y);
            WH(kt, wl, 2*ac+1) = r2h(w.z, w.w);
        }
    }
    __syncthreads();

    const int r = lane >> 2, c = lane & 3;
    const int arow = tid >> 2;                // staging row 0..63
    const int kw = (tid & 3) * 4;             // staging u32-word base

    for (int t = 0; t < 512; ++t) {
        const unsigned* hp = t ? (HPbase + (size_t)(t - 1) * 65536) : hp0;
        const unsigned* src = hp + (size_t)(m0 + arow) * 256 + kw;

        float acc[2][2][4];
#pragma unroll
        for (int mf = 0; mf < 2; ++mf)
#pragma unroll
            for (int nf = 0; nf < 2; ++nf)
#pragma unroll
                for (int i = 0; i < 4; ++i) acc[mf][nf][i] = 0.f;

        // --- stage chunk 0 ---
        uint4 v0[8];
#pragma unroll
        for (int i = 0; i < 8; ++i) v0[i] = *(const uint4*)(src + i * 16);
#pragma unroll
        for (int i = 0; i < 8; ++i) {
            const int w = kw + i * 16;
            const int kt2 = w >> 3, wq = w & 7;
            AH(kt2, arow, wq)     = v0[i].x;
            AH(kt2, arow, wq + 1) = v0[i].y;
            AH(kt2, arow, wq + 2) = v0[i].z;
            AH(kt2, arow, wq + 3) = v0[i].w;
        }
        __syncthreads();

        // --- prefetch chunk 1 into registers (hidden under chunk-0 mma) ---
        uint4 v1[8];
#pragma unroll
        for (int i = 0; i < 8; ++i) v1[i] = *(const uint4*)(src + 128 + i * 16);

        // --- chunk 0 mma (barrier-free) ---
#pragma unroll 4
        for (int kt2 = 0; kt2 < 16; ++kt2) {
            unsigned ah[2][4], bh[2][2];
#pragma unroll
            for (int mf = 0; mf < 2; ++mf) {
                const int mm = mbw + mf * 16;
                ah[mf][0] = AH(kt2, mm + r,     c);
                ah[mf][1] = AH(kt2, mm + r + 8, c);
                ah[mf][2] = AH(kt2, mm + r,     c + 4);
                ah[mf][3] = AH(kt2, mm + r + 8, c + 4);
            }
#pragma unroll
            for (int nf = 0; nf < 2; ++nf) {
                const int nn = nb0 + nf * 8 + r;
                bh[nf][0] = WH(kt2, nn, c);
                bh[nf][1] = WH(kt2, nn, c + 4);
            }
#pragma unroll
            for (int mf = 0; mf < 2; ++mf)
#pragma unroll
                for (int nf = 0; nf < 2; ++nf)
                    mma_f16(acc[mf][nf], ah[mf], bh[nf]);
        }
        __syncthreads();

        // --- stage chunk 1 from registers ---
#pragma unroll
        for (int i = 0; i < 8; ++i) {
            const int w = kw + i * 16;
            const int kt2 = w >> 3, wq = w & 7;
            AH(kt2, arow, wq)     = v1[i].x;
            AH(kt2, arow, wq + 1) = v1[i].y;
            AH(kt2, arow, wq + 2) = v1[i].z;
            AH(kt2, arow, wq + 3) = v1[i].w;
        }
        __syncthreads();

        // --- chunk 1 mma ---
#pragma unroll 4
        for (int kt2 = 0; kt2 < 16; ++kt2) {
            const int ktw = 16 + kt2;
            unsigned ah[2][4], bh[2][2];
#pragma unroll
            for (int mf = 0; mf < 2; ++mf) {
                const int mm = mbw + mf * 16;
                ah[mf][0] = AH(kt2, mm + r,     c);
                ah[mf][1] = AH(kt2, mm + r + 8, c);
                ah[mf][2] = AH(kt2, mm + r,     c + 4);
                ah[mf][3] = AH(kt2, mm + r + 8, c + 4);
            }
#pragma unroll
            for (int nf = 0; nf < 2; ++nf) {
                const int nn = nb0 + nf * 8 + r;
                bh[nf][0] = WH(ktw, nn, c);
                bh[nf][1] = WH(ktw, nn, c + 4);
            }
#pragma unroll
            for (int mf = 0; mf < 2; ++mf)
#pragma unroll
                for (int nf = 0; nf < 2; ++nf)
                    mma_f16(acc[mf][nf], ah[mf], bh[nf]);
        }
        __syncthreads();   // A buffer dead; Gs aliasing safe

        // --- stage gates into SMEM ---
        {
            const int c2 = (lane & 3) * 2;
#pragma unroll
            for (int mf = 0; mf < 2; ++mf)
#pragma unroll
                for (int nf = 0; nf < 2; ++nf) {
                    const int rl = mbw + mf * 16 + r;
                    const int cl = nb0 + nf * 8 + c2;
                    Gs[rl * 65 + cl]           = acc[mf][nf][0];
                    Gs[rl * 65 + cl + 1]       = acc[mf][nf][1];
                    Gs[(rl + 8) * 65 + cl]     = acc[mf][nf][2];
                    Gs[(rl + 8) * 65 + cl + 1] = acc[mf][nf][3];
                }
        }
        __syncthreads();

        // --- gate nonlinearities + c/h update (2 adjacent j per thread) ---
        {
            const float* xpt = XP + (size_t)t * 524288;
            float* hout = Hbase + (size_t)t * 131072;
            unsigned* hpout = HPbase + (size_t)t * 65536;
            const int j2 = (tid & 7) * 2;
            const int mr = tid >> 3;            // 0..31
#pragma unroll
            for (int p = 0; p < 2; ++p) {
                const int m = mr + p * 32;
                const int b = m0 + m;
                const int jg = j0 + j2;
                const float* xr = xpt + (size_t)b * 2048;
                const float2 xi = *(const float2*)(xr + jg);
                const float2 xf = *(const float2*)(xr + 512 + jg);
                const float2 xg = *(const float2*)(xr + 1024 + jg);
                const float2 xo = *(const float2*)(xr + 1536 + jg);
                float* cp = cbuf + (size_t)b * 512 + jg;
                const float2 cc = *(const float2*)cp;
                const float* gr = Gs + m * 65 + j2;

                const float i0 = sigf(xi.x + gr[0]);
                const float i1 = sigf(xi.y + gr[1]);
                const float f0 = sigf(xf.x + gr[16]);
                const float f1 = sigf(xf.y + gr[17]);
                const float g0 = tanhf_(xg.x + gr[32]);
                const float g1 = tanhf_(xg.y + gr[33]);
                const float o0 = sigf(xo.x + gr[48]);
                const float o1 = sigf(xo.y + gr[49]);
                const float c0 = f0 * cc.x + i0 * g0;
                const float c1 = f1 * cc.y + i1 * g1;
                *(float2*)cp = make_float2(c0, c1);
                const float h0 = o0 * tanhf_(c0);
                const float h1 = o1 * tanhf_(c1);
                *(float2*)(hout + (size_t)b * 512 + jg) = make_float2(h0, h1);
                hpout[(size_t)b * 256 + (jg >> 1)] = r2h(h0, h1);
            }
        }

        // --- grid-wide barrier (monotonic counter; reset before launch) ---
        __threadfence();
        __syncthreads();
        if (tid == 0) {
            atomicAdd(bar, 1u);
            const unsigned target = 128u * (unsigned)(t + 1);
            while (*(volatile unsigned*)bar < target) { }
        }
        __syncthreads();
    }
}

// ---------------------------------------------------------------------------
__global__ void zero_kernel(float* __restrict__ p, int n, unsigned* __restrict__ bar) {
    const int i = blockIdx.x * 256 + threadIdx.x;
    if (i < n) p[i] = 0.f;
    if (i == 0) *bar = 0u;
}

__global__ void final_kernel(
    const float* __restrict__ hlast,
    const float* __restrict__ Wl, const float* __restrict__ bl,
    float* __restrict__ y)
{
    const int b = blockIdx.x * 8 + (threadIdx.x >> 5);
    const int lane = threadIdx.x & 31;
    const float* hr = hlast + (size_t)b * 512;
    float s = 0.f;
    for (int k = lane; k < 512; k += 32) s += hr[k] * Wl[k];
#pragma unroll
    for (int o = 16; o; o >>= 1) s += __shfl_xor_sync(0xffffffffu, s, o);
    if (lane == 0) y[b] = s + bl[0];
}

// ---------------------------------------------------------------------------
extern "C" void kernel_launch(void* const* d_in, const int* in_sizes, int n_in,
                              void* d_out, int out_size)
{
    const float* X     = (const float*)d_in[0];
    const float* W_ih0 = (const float*)d_in[1];
    const float* W_hh0 = (const float*)d_in[2];
    const float* b_ih0 = (const float*)d_in[3];
    const float* b_hh0 = (const float*)d_in[4];
    const float* W_ih1 = (const float*)d_in[5];
    const float* W_hh1 = (const float*)d_in[6];
    const float* b_ih1 = (const float*)d_in[7];
    const float* b_hh1 = (const float*)d_in[8];
    const float* W_lin = (const float*)d_in[9];
    const float* b_lin = (const float*)d_in[10];
    float* y = (float*)d_out;

    float *XP, *Hb, *Cb, *Zb;
    unsigned *HPb, *bar;
    cudaGetSymbolAddress((void**)&XP, g_XP);
    cudaGetSymbolAddress((void**)&Hb, g_H);
    cudaGetSymbolAddress((void**)&HPb, g_HP);
    cudaGetSymbolAddress((void**)&Cb, g_C);
    cudaGetSymbolAddress((void**)&Zb, g_Z);
    cudaGetSymbolAddress((void**)&bar, g_bar);

    static bool attr_done = false;
    if (!attr_done) {
        cudaFuncSetAttribute(lstm_persist_kernel,
                             cudaFuncAttributeMaxDynamicSharedMemorySize, PSMEM);
        attr_done = true;
    }

    // Layer 0
    zero_kernel<<<512, 256>>>(Cb, 256 * 512, bar);
    proj_kernel<<<dim3(1024, 32), 256>>>(X, 131072, 256, 256, W_ih0, b_ih0, b_hh0, XP);
    lstm_persist_kernel<<<128, 256, PSMEM>>>((const unsigned*)Zb, W_hh0, XP, Hb, HPb, Cb, bar);

    // Layer 1
    proj_kernel<<<dim3(1024, 32), 256>>>(Hb, 512, 131072, 512, W_ih1, b_ih1, b_hh1, XP);
    zero_kernel<<<512, 256>>>(Cb, 256 * 512, bar);
    lstm_persist_kernel<<<128, 256, PSMEM>>>((const unsigned*)Zb, W_hh1, XP, Hb, HPb, Cb, bar);

    final_kernel<<<32, 256>>>(Hb + (size_t)511 * 131072, W_lin, b_lin, y);
}

// round 13
// speedup vs baseline: 1.6830x; 1.0600x over previous
#include <cuda_runtime.h>
#include <cuda_fp16.h>
#include <cstdint>
#include <cstddef>

// Problem sizes: B=256, T=512, I=256, H=512, 4H=2048
// Layouts: g_XP [T,B,4H] fp32, g_HP [T,B,H] fp16 (half2 packed, 2/u32)

__device__ float    g_XP[(size_t)512 * 256 * 2048]; // 1 GiB input projections
__device__ unsigned g_HP[(size_t)512 * 256 * 256];  // fp16 hidden states (2/u32)
__device__ float    g_Z [256 * 512];                // zeros (h_{-1}; any view)
__device__ unsigned g_bar;                          // grid barrier counter

__device__ __forceinline__ unsigned pack2h(__half a, __half b) {
    __half2 t = __halves2half2(a, b);
    return *reinterpret_cast<unsigned*>(&t);
}
__device__ __forceinline__ unsigned r2h(float a, float b) {
    __half2 t = __floats2half2_rn(a, b);
    return *reinterpret_cast<unsigned*>(&t);
}

// Split float4 into hi/lo fp16x2 words (k-even in low half).
__device__ __forceinline__ void split4h(float4 v, unsigned& h0, unsigned& h1,
                                        unsigned& l0, unsigned& l1) {
    __half hx = __float2half(v.x), hy = __float2half(v.y);
    __half hz = __float2half(v.z), hw = __float2half(v.w);
    h0 = pack2h(hx, hy);
    h1 = pack2h(hz, hw);
    l0 = r2h(v.x - __half2float(hx), v.y - __half2float(hy));
    l1 = r2h(v.z - __half2float(hz), v.w - __half2float(hw));
}

__device__ __forceinline__ void mma_f16(float* d, const unsigned* a, const unsigned* b) {
    asm volatile(
        "mma.sync.aligned.m16n8k16.row.col.f32.f16.f16.f32 "
        "{%0,%1,%2,%3}, {%4,%5,%6,%7}, {%8,%9}, {%0,%1,%2,%3};\n"
        : "+f"(d[0]), "+f"(d[1]), "+f"(d[2]), "+f"(d[3])
        : "r"(a[0]), "r"(a[1]), "r"(a[2]), "r"(a[3]), "r"(b[0]), "r"(b[1]));
}

__device__ __forceinline__ float sigf(float x)   { return 1.f / (1.f + __expf(-x)); }
__device__ __forceinline__ float tanhf_(float x) { return 2.f / (1.f + __expf(-2.f * x)) - 1.f; }

// ---------------------------------------------------------------------------
// proj_kernel: out[t,b,0:2048] = A_row(b,t)[0:K] @ W[2048,K]^T + bias1 + bias2
// fp16 2-term (W split hi/lo; A single-rounded). Dual A path:
//   Ah != nullptr -> A is fp16-packed [.., sAb/sAt in u32 units]
//   else          -> A is fp32       [.., sAb/sAt in float units]
// Row address for (batch b, time t): b*sAb + t*sAt.
// CTA 128m x 64n, BK=16, 8 warps (4x2), warp tile 32m x 32n.
// ---------------------------------------------------------------------------
__global__ void __launch_bounds__(256) proj_kernel(
    const float* __restrict__ Af, const unsigned* __restrict__ Ah,
    int sAb, int sAt, int K,
    const float* __restrict__ W,
    const float* __restrict__ bias1, const float* __restrict__ bias2,
    float* __restrict__ out)
{
    __shared__ unsigned As [2][128][9];
    __shared__ unsigned WsH[2][64][9], WsL[2][64][9];

    const int tid  = threadIdx.x;
    const int lane = tid & 31;
    const int warp = tid >> 5;
    const int wr = warp >> 1, wc = warp & 1;
    const int m0 = blockIdx.x * 128;
    const int bb = m0 >> 9;
    const int tt0 = m0 & 511;
    const int n0 = blockIdx.y * 64;

    const int ar0 = tid >> 2, ac = tid & 3;
    const int wrow = tid >> 2;

    const bool f16a = (Ah != nullptr);
    const float*    Ar0f = Af ? (Af + (size_t)bb * sAb + (size_t)(tt0 + ar0) * sAt + ac * 4) : nullptr;
    const float*    Ar1f = Af ? (Ar0f + (size_t)64 * sAt) : nullptr;
    const unsigned* Ar0h = Ah ? (Ah + (size_t)bb * sAb + (size_t)(tt0 + ar0) * sAt + ac * 2) : nullptr;
    const unsigned* Ar1h = Ah ? (Ar0h + (size_t)64 * sAt) : nullptr;
    const float* Wr = W + (size_t)(n0 + wrow) * K;

    const int nkt = K >> 4;

    float acc[2][4][4];
#pragma unroll
    for (int f = 0; f < 2; ++f)
#pragma unroll
        for (int n = 0; n < 4; ++n)
#pragma unroll
            for (int i = 0; i < 4; ++i) acc[f][n][i] = 0.f;

    float4 ra0, ra1;
    uint2  ua0, ua1;
    float4 rw = *(const float4*)(Wr + ac * 4);
    if (f16a) {
        ua0 = *(const uint2*)(Ar0h);
        ua1 = *(const uint2*)(Ar1h);
        As[0][ar0][2*ac]      = ua0.x; As[0][ar0][2*ac+1]    = ua0.y;
        As[0][ar0+64][2*ac]   = ua1.x; As[0][ar0+64][2*ac+1] = ua1.y;
    } else {
        ra0 = *(const float4*)(Ar0f);
        ra1 = *(const float4*)(Ar1f);
        As[0][ar0][2*ac]      = r2h(ra0.x, ra0.y);
        As[0][ar0][2*ac+1]    = r2h(ra0.z, ra0.w);
        As[0][ar0+64][2*ac]   = r2h(ra1.x, ra1.y);
        As[0][ar0+64][2*ac+1] = r2h(ra1.z, ra1.w);
    }
    {
        unsigned h0, h1, l0, l1;
        split4h(rw, h0, h1, l0, l1);
        WsH[0][wrow][2*ac] = h0; WsH[0][wrow][2*ac+1] = h1;
        WsL[0][wrow][2*ac] = l0; WsL[0][wrow][2*ac+1] = l1;
    }
    __syncthreads();

    int cur = 0;
    for (int kt = 0; kt < nkt; ++kt) {
        const bool pf = (kt + 1 < nkt);
        if (pf) {
            if (f16a) {
                ua0 = *(const uint2*)(Ar0h + (kt + 1) * 8);
                ua1 = *(const uint2*)(Ar1h + (kt + 1) * 8);
            } else {
                ra0 = *(const float4*)(Ar0f + (kt + 1) * 16);
                ra1 = *(const float4*)(Ar1f + (kt + 1) * 16);
            }
            rw = *(const float4*)(Wr + (kt + 1) * 16 + ac * 4);
        }
        const int r = lane >> 2, c = lane & 3;
        unsigned ah[2][4], bh[4][2], bl[4][2];
#pragma unroll
        for (int f = 0; f < 2; ++f) {
            const int mb = wr * 32 + f * 16;
            ah[f][0] = As[cur][mb + r    ][c];
            ah[f][1] = As[cur][mb + r + 8][c];
            ah[f][2] = As[cur][mb + r    ][c + 4];
            ah[f][3] = As[cur][mb + r + 8][c + 4];
        }
#pragma unroll
        for (int n = 0; n < 4; ++n) {
            const int nb = wc * 32 + n * 8 + r;
            bh[n][0] = WsH[cur][nb][c];
            bh[n][1] = WsH[cur][nb][c + 4];
            bl[n][0] = WsL[cur][nb][c];
            bl[n][1] = WsL[cur][nb][c + 4];
        }
#pragma unroll
        for (int f = 0; f < 2; ++f)
#pragma unroll
            for (int n = 0; n < 4; ++n) {
                mma_f16(acc[f][n], ah[f], bh[n]);
                mma_f16(acc[f][n], ah[f], bl[n]);
            }
        if (pf) {
            const int nxt = cur ^ 1;
            if (f16a) {
                As[nxt][ar0][2*ac]      = ua0.x; As[nxt][ar0][2*ac+1]    = ua0.y;
                As[nxt][ar0+64][2*ac]   = ua1.x; As[nxt][ar0+64][2*ac+1] = ua1.y;
            } else {
                As[nxt][ar0][2*ac]      = r2h(ra0.x, ra0.y);
                As[nxt][ar0][2*ac+1]    = r2h(ra0.z, ra0.w);
                As[nxt][ar0+64][2*ac]   = r2h(ra1.x, ra1.y);
                As[nxt][ar0+64][2*ac+1] = r2h(ra1.z, ra1.w);
            }
            unsigned h0, h1, l0, l1;
            split4h(rw, h0, h1, l0, l1);
            WsH[nxt][wrow][2*ac] = h0; WsH[nxt][wrow][2*ac+1] = h1;
            WsL[nxt][wrow][2*ac] = l0; WsL[nxt][wrow][2*ac+1] = l1;
        }
        __syncthreads();
        cur ^= 1;
    }

    const int r = lane >> 2, c2 = (lane & 3) * 2;
#pragma unroll
    for (int f = 0; f < 2; ++f) {
#pragma unroll
        for (int n = 0; n < 4; ++n) {
            const int tloc = tt0 + wr * 32 + f * 16 + r;
            const int col = n0 + wc * 32 + n * 8 + c2;
            const float bb0 = bias1[col] + bias2[col];
            const float bb1 = bias1[col + 1] + bias2[col + 1];
            float* o0 = out + (size_t)tloc * 524288 + (size_t)bb * 2048 + col;
            o0[0]    = acc[f][n][0] + bb0;
            o0[1]    = acc[f][n][1] + bb1;
            float* o1 = out + (size_t)(tloc + 8) * 524288 + (size_t)bb * 2048 + col;
            o1[0]    = acc[f][n][2] + bb0;
            o1[1]    = acc[f][n][3] + bb1;
        }
    }
}

// ---------------------------------------------------------------------------
// lstm_persist_kernel v5: all 512 timesteps of one layer in one launch.
// 128 CTAs (1/SM), 256 threads (8 warps as 2m x 4n, warp tile 32m x 16n).
// CTA = 64 batch rows x 16 hidden units (64 gathered gate cols).
// Single-term fp16 mma. Per step: single full-K stage (32 k-tiles) -> one
// barrier-free mma loop. Cell state c lives in REGISTERS (thread<->(b,j) map
// fixed). XP biases for step t+1 prefetched into registers before the grid
// barrier (DRAM latency hidden under barrier wait). h stored fp16-only.
// Dynamic SMEM (u32): WsH 18432 + As 18432 = 36864 w = 147,456 B. Gs alias As.
// ---------------------------------------------------------------------------
#define WH(kt,row,cc) WsH[(kt)*576 + (row)*9 + (cc)]
#define AH(kt,row,cc) As [(kt)*576 + (row)*9 + (cc)]
#define PSMEM (36864 * 4)

__global__ void __launch_bounds__(256) lstm_persist_kernel(
    const unsigned* __restrict__ hp0,  // fp16 h_{-1} (zeros), row = 256 u32
    const float* __restrict__ Whh,     // [2048, 512]
    const float* __restrict__ XP,      // [T,B,4H]
    unsigned* __restrict__ HPbase,     // [T,B,H] fp16, t-slab = 65536 u32
    unsigned* __restrict__ bar)
{
    extern __shared__ unsigned smem_u[];
    unsigned* WsH = smem_u;
    unsigned* As  = WsH + 18432;
    float*    Gs  = (float*)As;        // alias: used only after all mma done

    const int tid  = threadIdx.x;
    const int lane = tid & 31;
    const int warp = tid >> 5;
    const int mbw = (warp >> 2) * 32;        // warp m base (0/32)
    const int nb0 = (warp & 3) * 16;         // warp n base (0..48)
    const int m0 = (blockIdx.x & 3) * 64;    // batch base
    const int j0 = (blockIdx.x >> 2) * 16;   // hidden-unit base

    const int wl = tid >> 2;                              // local gate col 0..63
    const int ac = tid & 3;
    const int grow = ((wl >> 4) << 9) + j0 + (wl & 15);   // gate row in W_hh

    // --- load W tile into SMEM once (single-rounded fp16) ---
    {
        const float* Wr = Whh + (size_t)grow * 512;
        for (int kt = 0; kt < 32; ++kt) {
            float4 w = *(const float4*)(Wr + kt * 16 + ac * 4);
            WH(kt, wl, 2*ac)   = r2h(w.x, w.y);
            WH(kt, wl, 2*ac+1) = r2h(w.z, w.w);
        }
    }
    __syncthreads();

    const int r = lane >> 2, c = lane & 3;
    const int arow = tid >> 2;                // staging row 0..63
    const int kw = (tid & 3) * 4;             // staging u32-word base

    // --- epilogue thread mapping (fixed across t) + register state ---
    const int j2 = (tid & 7) * 2;             // 0..14
    const int mr = tid >> 3;                  // 0..31 (m = mr, mr+32)
    float crg[2][2] = {{0.f, 0.f}, {0.f, 0.f}};   // cell state registers
    float2 pxi[2], pxf[2], pxg[2], pxo[2];        // prefetched XP biases

    // prefetch XP for t = 0
#pragma unroll
    for (int p = 0; p < 2; ++p) {
        const int b = m0 + mr + p * 32;
        const float* xr = XP + (size_t)b * 2048 + j0 + j2;
        pxi[p] = *(const float2*)(xr);
        pxf[p] = *(const float2*)(xr + 512);
        pxg[p] = *(const float2*)(xr + 1024);
        pxo[p] = *(const float2*)(xr + 1536);
    }

    for (int t = 0; t < 512; ++t) {
        const unsigned* hp = t ? (HPbase + (size_t)(t - 1) * 65536) : hp0;
        const unsigned* src = hp + (size_t)(m0 + arow) * 256 + kw;

        // --- stage full K (64 rows x 256 u32) — pure uint4 copy ---
#pragma unroll
        for (int i = 0; i < 16; ++i) {
            const int w = kw + i * 16;               // 0..252
            uint4 v = *(const uint4*)(src + i * 16);
            const int kt2 = w >> 3, wq = w & 7;      // kt 0..31, wq 0 or 4
            AH(kt2, arow, wq)     = v.x;
            AH(kt2, arow, wq + 1) = v.y;
            AH(kt2, arow, wq + 2) = v.z;
            AH(kt2, arow, wq + 3) = v.w;
        }
        __syncthreads();

        float acc[2][2][4];
#pragma unroll
        for (int mf = 0; mf < 2; ++mf)
#pragma unroll
            for (int nf = 0; nf < 2; ++nf)
#pragma unroll
                for (int i = 0; i < 4; ++i) acc[mf][nf][i] = 0.f;

        // --- barrier-free mma loop over all 32 k-tiles ---
#pragma unroll 4
        for (int kt = 0; kt < 32; ++kt) {
            unsigned ah[2][4], bh[2][2];
#pragma unroll
            for (int mf = 0; mf < 2; ++mf) {
                const int mm = mbw + mf * 16;
                ah[mf][0] = AH(kt, mm + r,     c);
                ah[mf][1] = AH(kt, mm + r + 8, c);
                ah[mf][2] = AH(kt, mm + r,     c + 4);
                ah[mf][3] = AH(kt, mm + r + 8, c + 4);
            }
#pragma unroll
            for (int nf = 0; nf < 2; ++nf) {
                const int nn = nb0 + nf * 8 + r;
                bh[nf][0] = WH(kt, nn, c);
                bh[nf][1] = WH(kt, nn, c + 4);
            }
#pragma unroll
            for (int mf = 0; mf < 2; ++mf)
#pragma unroll
                for (int nf = 0; nf < 2; ++nf)
                    mma_f16(acc[mf][nf], ah[mf], bh[nf]);
        }
        __syncthreads();   // A buffer dead; Gs aliasing safe

        // --- stage gates into SMEM ---
        {
            const int c2 = (lane & 3) * 2;
#pragma unroll
            for (int mf = 0; mf < 2; ++mf)
#pragma unroll
                for (int nf = 0; nf < 2; ++nf) {
                    const int rl = mbw + mf * 16 + r;
                    const int cl = nb0 + nf * 8 + c2;
                    Gs[rl * 65 + cl]           = acc[mf][nf][0];
                    Gs[rl * 65 + cl + 1]       = acc[mf][nf][1];
                    Gs[(rl + 8) * 65 + cl]     = acc[mf][nf][2];
                    Gs[(rl + 8) * 65 + cl + 1] = acc[mf][nf][3];
                }
        }
        __syncthreads();

        // --- gate nonlinearities + c/h update (pure ALU; XP preloaded) ---
        {
            unsigned* hpout = HPbase + (size_t)t * 65536;
#pragma unroll
            for (int p = 0; p < 2; ++p) {
                const int m = mr + p * 32;
                const int b = m0 + m;
                const float* gr = Gs + m * 65 + j2;
                const float i0 = sigf(pxi[p].x + gr[0]);
                const float i1 = sigf(pxi[p].y + gr[1]);
                const float f0 = sigf(pxf[p].x + gr[16]);
                const float f1 = sigf(pxf[p].y + gr[17]);
                const float g0 = tanhf_(pxg[p].x + gr[32]);
                const float g1 = tanhf_(pxg[p].y + gr[33]);
                const float o0 = sigf(pxo[p].x + gr[48]);
                const float o1 = sigf(pxo[p].y + gr[49]);
                const float c0 = f0 * crg[p][0] + i0 * g0;
                const float c1 = f1 * crg[p][1] + i1 * g1;
                crg[p][0] = c0; crg[p][1] = c1;
                const float h0 = o0 * tanhf_(c0);
                const float h1 = o1 * tanhf_(c1);
                hpout[(size_t)b * 256 + ((j0 + j2) >> 1)] = r2h(h0, h1);
            }
        }

        // --- prefetch XP for t+1 (hidden under grid-barrier wait) ---
        if (t + 1 < 512) {
#pragma unroll
            for (int p = 0; p < 2; ++p) {
                const int b = m0 + mr + p * 32;
                const float* xr = XP + (size_t)(t + 1) * 524288
                                + (size_t)b * 2048 + j0 + j2;
                pxi[p] = *(const float2*)(xr);
                pxf[p] = *(const float2*)(xr + 512);
                pxg[p] = *(const float2*)(xr + 1024);
                pxo[p] = *(const float2*)(xr + 1536);
            }
        }

        // --- grid-wide barrier (monotonic counter; reset before launch) ---
        __threadfence();
        __syncthreads();
        if (tid == 0) {
            atomicAdd(bar, 1u);
            const unsigned target = 128u * (unsigned)(t + 1);
            while (*(volatile unsigned*)bar < target) { }
        }
        __syncthreads();
    }
}

// ---------------------------------------------------------------------------
__global__ void reset_bar(unsigned* __restrict__ bar) { *bar = 0u; }

__global__ void final_kernel(
    const unsigned* __restrict__ hlast,   // fp16 h[T-1] slab, row = 256 u32
    const float* __restrict__ Wl, const float* __restrict__ bl,
    float* __restrict__ y)
{
    const int b = blockIdx.x * 8 + (threadIdx.x >> 5);
    const int lane = threadIdx.x & 31;
    const unsigned* hr = hlast + (size_t)b * 256;
    float s = 0.f;
    for (int k = lane; k < 256; k += 32) {
        const __half2 v = *reinterpret_cast<const __half2*>(hr + k);
        s += __half2float(__low2half(v))  * Wl[2 * k]
           + __half2float(__high2half(v)) * Wl[2 * k + 1];
    }
#pragma unroll
    for (int o = 16; o; o >>= 1) s += __shfl_xor_sync(0xffffffffu, s, o);
    if (lane == 0) y[b] = s + bl[0];
}

// ---------------------------------------------------------------------------
extern "C" void kernel_launch(void* const* d_in, const int* in_sizes, int n_in,
                              void* d_out, int out_size)
{
    const float* X     = (const float*)d_in[0];
    const float* W_ih0 = (const float*)d_in[1];
    const float* W_hh0 = (const float*)d_in[2];
    const float* b_ih0 = (const float*)d_in[3];
    const float* b_hh0 = (const float*)d_in[4];
    const float* W_ih1 = (const float*)d_in[5];
    const float* W_hh1 = (const float*)d_in[6];
    const float* b_ih1 = (const float*)d_in[7];
    const float* b_hh1 = (const float*)d_in[8];
    const float* W_lin = (const float*)d_in[9];
    const float* b_lin = (const float*)d_in[10];
    float* y = (float*)d_out;

    float *XP, *Zb;
    unsigned *HPb, *bar;
    cudaGetSymbolAddress((void**)&XP, g_XP);
    cudaGetSymbolAddress((void**)&HPb, g_HP);
    cudaGetSymbolAddress((void**)&Zb, g_Z);
    cudaGetSymbolAddress((void**)&bar, g_bar);

    static bool attr_done = false;
    if (!attr_done) {
        cudaFuncSetAttribute(lstm_persist_kernel,
                             cudaFuncAttributeMaxDynamicSharedMemorySize, PSMEM);
        attr_done = true;
    }

    // Layer 0: proj from fp32 X (X is [B,T,I]: sAb=T*I=131072, sAt=I=256)
    reset_bar<<<1, 1>>>(bar);
    proj_kernel<<<dim3(1024, 32), 256>>>(X, nullptr, 131072, 256, 256,
                                         W_ih0, b_ih0, b_hh0, XP);
    lstm_persist_kernel<<<128, 256, PSMEM>>>((const unsigned*)Zb, W_hh0, XP, HPb, bar);

    // Layer 1: proj from fp16 h, t-major [T,B,H]: sAb=256 u32, sAt=65536 u32
    proj_kernel<<<dim3(1024, 32), 256>>>(nullptr, HPb, 256, 65536, 512,
                                         W_ih1, b_ih1, b_hh1, XP);
    reset_bar<<<1, 1>>>(bar);
    lstm_persist_kernel<<<128, 256, PSMEM>>>((const unsigned*)Zb, W_hh1, XP, HPb, bar);

    final_kernel<<<32, 256>>>(HPb + (size_t)511 * 65536, W_lin, b_lin, y);
}

// round 15
// speedup vs baseline: 1.8264x; 1.0852x over previous
#include <cuda_runtime.h>
#include <cuda_fp16.h>
#include <cstdint>
#include <cstddef>

// Problem sizes: B=256, T=512, I=256, H=512, 4H=2048
// Layouts: g_XP [T,B,4H] fp32, g_HP [T,B,H] fp16 (half2 packed, 2/u32)

__device__ float    g_XP[(size_t)512 * 256 * 2048]; // 1 GiB input projections
__device__ unsigned g_HP[(size_t)512 * 256 * 256];  // fp16 hidden states (2/u32)
__device__ float    g_Z [256 * 512];                // zeros (h_{-1}; any view)
__device__ unsigned g_bars[32 * 64];                // 32 barrier counters, 256B apart

__device__ __forceinline__ unsigned pack2h(__half a, __half b) {
    __half2 t = __halves2half2(a, b);
    return *reinterpret_cast<unsigned*>(&t);
}
__device__ __forceinline__ unsigned r2h(float a, float b) {
    __half2 t = __floats2half2_rn(a, b);
    return *reinterpret_cast<unsigned*>(&t);
}

// Split float4 into hi/lo fp16x2 words (k-even in low half).
__device__ __forceinline__ void split4h(float4 v, unsigned& h0, unsigned& h1,
                                        unsigned& l0, unsigned& l1) {
    __half hx = __float2half(v.x), hy = __float2half(v.y);
    __half hz = __float2half(v.z), hw = __float2half(v.w);
    h0 = pack2h(hx, hy);
    h1 = pack2h(hz, hw);
    l0 = r2h(v.x - __half2float(hx), v.y - __half2float(hy));
    l1 = r2h(v.z - __half2float(hz), v.w - __half2float(hw));
}

__device__ __forceinline__ void mma_f16(float* d, const unsigned* a, const unsigned* b) {
    asm volatile(
        "mma.sync.aligned.m16n8k16.row.col.f32.f16.f16.f32 "
        "{%0,%1,%2,%3}, {%4,%5,%6,%7}, {%8,%9}, {%0,%1,%2,%3};\n"
        : "+f"(d[0]), "+f"(d[1]), "+f"(d[2]), "+f"(d[3])
        : "r"(a[0]), "r"(a[1]), "r"(a[2]), "r"(a[3]), "r"(b[0]), "r"(b[1]));
}

__device__ __forceinline__ void ldsm_x4(unsigned& r0, unsigned& r1,
                                        unsigned& r2, unsigned& r3, unsigned addr) {
    asm volatile("ldmatrix.sync.aligned.m8n8.x4.shared.b16 {%0,%1,%2,%3}, [%4];"
        : "=r"(r0), "=r"(r1), "=r"(r2), "=r"(r3) : "r"(addr));
}
__device__ __forceinline__ uint32_t smem_u32(const void* p) {
    uint32_t a;
    asm("{ .reg .u64 t; cvta.to.shared.u64 t, %1; cvt.u32.u64 %0, t; }" : "=r"(a) : "l"(p));
    return a;
}

__device__ __forceinline__ float sigf(float x)   { return 1.f / (1.f + __expf(-x)); }
__device__ __forceinline__ float tanhf_(float x) { return 2.f / (1.f + __expf(-2.f * x)) - 1.f; }

// ---------------------------------------------------------------------------
// proj_kernel: out[t,b,0:2048] = A_row(b,t)[0:K] @ W[2048,K]^T + bias1 + bias2
// fp16 2-term (W split hi/lo; A single-rounded). Unchanged (validated R13).
// ---------------------------------------------------------------------------
__global__ void __launch_bounds__(256) proj_kernel(
    const float* __restrict__ Af, const unsigned* __restrict__ Ah,
    int sAb, int sAt, int K,
    const float* __restrict__ W,
    const float* __restrict__ bias1, const float* __restrict__ bias2,
    float* __restrict__ out)
{
    __shared__ unsigned As [2][128][9];
    __shared__ unsigned WsH[2][64][9], WsL[2][64][9];

    const int tid  = threadIdx.x;
    const int lane = tid & 31;
    const int warp = tid >> 5;
    const int wr = warp >> 1, wc = warp & 1;
    const int m0 = blockIdx.x * 128;
    const int bb = m0 >> 9;
    const int tt0 = m0 & 511;
    const int n0 = blockIdx.y * 64;

    const int ar0 = tid >> 2, ac = tid & 3;
    const int wrow = tid >> 2;

    const bool f16a = (Ah != nullptr);
    const float*    Ar0f = Af ? (Af + (size_t)bb * sAb + (size_t)(tt0 + ar0) * sAt + ac * 4) : nullptr;
    const float*    Ar1f = Af ? (Ar0f + (size_t)64 * sAt) : nullptr;
    const unsigned* Ar0h = Ah ? (Ah + (size_t)bb * sAb + (size_t)(tt0 + ar0) * sAt + ac * 2) : nullptr;
    const unsigned* Ar1h = Ah ? (Ar0h + (size_t)64 * sAt) : nullptr;
    const float* Wr = W + (size_t)(n0 + wrow) * K;

    const int nkt = K >> 4;

    float acc[2][4][4];
#pragma unroll
    for (int f = 0; f < 2; ++f)
#pragma unroll
        for (int n = 0; n < 4; ++n)
#pragma unroll
            for (int i = 0; i < 4; ++i) acc[f][n][i] = 0.f;

    float4 ra0, ra1;
    uint2  ua0, ua1;
    float4 rw = *(const float4*)(Wr + ac * 4);
    if (f16a) {
        ua0 = *(const uint2*)(Ar0h);
        ua1 = *(const uint2*)(Ar1h);
        As[0][ar0][2*ac]      = ua0.x; As[0][ar0][2*ac+1]    = ua0.y;
        As[0][ar0+64][2*ac]   = ua1.x; As[0][ar0+64][2*ac+1] = ua1.y;
    } else {
        ra0 = *(const float4*)(Ar0f);
        ra1 = *(const float4*)(Ar1f);
        As[0][ar0][2*ac]      = r2h(ra0.x, ra0.y);
        As[0][ar0][2*ac+1]    = r2h(ra0.z, ra0.w);
        As[0][ar0+64][2*ac]   = r2h(ra1.x, ra1.y);
        As[0][ar0+64][2*ac+1] = r2h(ra1.z, ra1.w);
    }
    {
        unsigned h0, h1, l0, l1;
        split4h(rw, h0, h1, l0, l1);
        WsH[0][wrow][2*ac] = h0; WsH[0][wrow][2*ac+1] = h1;
        WsL[0][wrow][2*ac] = l0; WsL[0][wrow][2*ac+1] = l1;
    }
    __syncthreads();

    int cur = 0;
    for (int kt = 0; kt < nkt; ++kt) {
        const bool pf = (kt + 1 < nkt);
        if (pf) {
            if (f16a) {
                ua0 = *(const uint2*)(Ar0h + (kt + 1) * 8);
                ua1 = *(const uint2*)(Ar1h + (kt + 1) * 8);
            } else {
                ra0 = *(const float4*)(Ar0f + (kt + 1) * 16);
                ra1 = *(const float4*)(Ar1f + (kt + 1) * 16);
            }
            rw = *(const float4*)(Wr + (kt + 1) * 16 + ac * 4);
        }
        const int r = lane >> 2, c = lane & 3;
        unsigned ah[2][4], bh[4][2], bl[4][2];
#pragma unroll
        for (int f = 0; f < 2; ++f) {
            const int mb = wr * 32 + f * 16;
            ah[f][0] = As[cur][mb + r    ][c];
            ah[f][1] = As[cur][mb + r + 8][c];
            ah[f][2] = As[cur][mb + r    ][c + 4];
            ah[f][3] = As[cur][mb + r + 8][c + 4];
        }
#pragma unroll
        for (int n = 0; n < 4; ++n) {
            const int nb = wc * 32 + n * 8 + r;
            bh[n][0] = WsH[cur][nb][c];
            bh[n][1] = WsH[cur][nb][c + 4];
            bl[n][0] = WsL[cur][nb][c];
            bl[n][1] = WsL[cur][nb][c + 4];
        }
#pragma unroll
        for (int f = 0; f < 2; ++f)
#pragma unroll
            for (int n = 0; n < 4; ++n) {
                mma_f16(acc[f][n], ah[f], bh[n]);
                mma_f16(acc[f][n], ah[f], bl[n]);
            }
        if (pf) {
            const int nxt = cur ^ 1;
            if (f16a) {
                As[nxt][ar0][2*ac]      = ua0.x; As[nxt][ar0][2*ac+1]    = ua0.y;
                As[nxt][ar0+64][2*ac]   = ua1.x; As[nxt][ar0+64][2*ac+1] = ua1.y;
            } else {
                As[nxt][ar0][2*ac]      = r2h(ra0.x, ra0.y);
                As[nxt][ar0][2*ac+1]    = r2h(ra0.z, ra0.w);
                As[nxt][ar0+64][2*ac]   = r2h(ra1.x, ra1.y);
                As[nxt][ar0+64][2*ac+1] = r2h(ra1.z, ra1.w);
            }
            unsigned h0, h1, l0, l1;
            split4h(rw, h0, h1, l0, l1);
            WsH[nxt][wrow][2*ac] = h0; WsH[nxt][wrow][2*ac+1] = h1;
            WsL[nxt][wrow][2*ac] = l0; WsL[nxt][wrow][2*ac+1] = l1;
        }
        __syncthreads();
        cur ^= 1;
    }

    const int r = lane >> 2, c2 = (lane & 3) * 2;
#pragma unroll
    for (int f = 0; f < 2; ++f) {
#pragma unroll
        for (int n = 0; n < 4; ++n) {
            const int tloc = tt0 + wr * 32 + f * 16 + r;
            const int col = n0 + wc * 32 + n * 8 + c2;
            const float bb0 = bias1[col] + bias2[col];
            const float bb1 = bias1[col + 1] + bias2[col + 1];
            float* o0 = out + (size_t)tloc * 524288 + (size_t)bb * 2048 + col;
            o0[0]    = acc[f][n][0] + bb0;
            o0[1]    = acc[f][n][1] + bb1;
            float* o1 = out + (size_t)(tloc + 8) * 524288 + (size_t)bb * 2048 + col;
            o1[0]    = acc[f][n][2] + bb0;
            o1[1]    = acc[f][n][3] + bb1;
        }
    }
}

// ---------------------------------------------------------------------------
// lstm_persist_kernel v6: all 512 timesteps of one layer in one launch.
// 128 CTAs (1/SM), 256 threads (8 warps, 2m x 4n, warp tile 32m x 16n).
// CTA = 64 batch rows x 16 hidden units (64 gathered gate cols).
// Changes vs v5: row stride 9->12 u32 (conflict-free ldmatrix phases),
// ldmatrix.x4 fragment loads (3 LDSM vs 12 LDS per warp-kt), Gs de-aliased
// (one fewer sync), distributed 32-counter grid barrier.
// Dynamic SMEM (u32): WsH 24576 + As 24576 + Gs 4160 = 53312 w = 213,248 B.
// ---------------------------------------------------------------------------
#define WH(kt,row,cc) WsH[(kt)*768 + (row)*12 + (cc)]
#define AH(kt,row,cc) As [(kt)*768 + (row)*12 + (cc)]
#define PSMEM (53312 * 4)

__global__ void __launch_bounds__(256) lstm_persist_kernel(
    const unsigned* __restrict__ hp0,  // fp16 h_{-1} (zeros), row = 256 u32
    const float* __restrict__ Whh,     // [2048, 512]
    const float* __restrict__ XP,      // [T,B,4H]
    unsigned* __restrict__ HPbase,     // [T,B,H] fp16, t-slab = 65536 u32
    unsigned* __restrict__ bars)       // 32 counters, stride 64 u32
{
    extern __shared__ unsigned smem_u[];
    unsigned* WsH = smem_u;            // 24576 u32
    unsigned* As  = WsH + 24576;       // 24576 u32
    float*    Gs  = (float*)(As + 24576); // 4160 u32

    const int tid  = threadIdx.x;
    const int lane = tid & 31;
    const int warp = tid >> 5;
    const int mbw = (warp >> 2) * 32;        // warp m base (0/32)
    const int nb0 = (warp & 3) * 16;         // warp n base (0..48)
    const int m0 = (blockIdx.x & 3) * 64;    // batch base
    const int j0 = (blockIdx.x >> 2) * 16;   // hidden-unit base

    const int wl = tid >> 2;                              // local gate col 0..63
    const int ac = tid & 3;
    const int grow = ((wl >> 4) << 9) + j0 + (wl & 15);   // gate row in W_hh

    // --- load W tile into SMEM once (single-rounded fp16) ---
    {
        const float* Wr = Whh + (size_t)grow * 512;
        for (int kt = 0; kt < 32; ++kt) {
            float4 w = *(const float4*)(Wr + kt * 16 + ac * 4);
            WH(kt, wl, 2*ac)   = r2h(w.x, w.y);
            WH(kt, wl, 2*ac+1) = r2h(w.z, w.w);
        }
    }
    __syncthreads();

    // --- ldmatrix per-lane base addresses (byte, shared space) ---
    // A (per mf): matrix q: row = mbw+mf*16 + (lane&7) + (q&1)*8, col4 = (q>>1)*4
    // B: matrix q: row = nb0 + (lane&7) + (q>>1)*8, col4 = (q&1)*4
    const uint32_t smW = smem_u32(WsH);
    const uint32_t smA = smem_u32(As);
    const int lq = lane >> 3, lr = lane & 7;
    uint32_t aAddr[2], bAddr;
#pragma unroll
    for (int mf = 0; mf < 2; ++mf) {
        const int row = mbw + mf * 16 + lr + (lq & 1) * 8;
        const int col4 = (lq >> 1) * 4;
        aAddr[mf] = smA + (uint32_t)(row * 12 + col4) * 4u;
    }
    {
        const int row = nb0 + lr + (lq >> 1) * 8;
        const int col4 = (lq & 1) * 4;
        bAddr = smW + (uint32_t)(row * 12 + col4) * 4u;
    }

    const int arow = tid >> 2;                // staging row 0..63
    const int kw = (tid & 3) * 4;             // staging u32-word base
    const int r = lane >> 2;

    // --- epilogue thread mapping (fixed across t) + register state ---
    const int j2 = (tid & 7) * 2;             // 0..14
    const int mr = tid >> 3;                  // 0..31 (m = mr, mr+32)
    float crg[2][2] = {{0.f, 0.f}, {0.f, 0.f}};   // cell state registers
    float2 pxi[2], pxf[2], pxg[2], pxo[2];        // prefetched XP biases

    // prefetch XP for t = 0
#pragma unroll
    for (int p = 0; p < 2; ++p) {
        const int b = m0 + mr + p * 32;
        const float* xr = XP + (size_t)b * 2048 + j0 + j2;
        pxi[p] = *(const float2*)(xr);
        pxf[p] = *(const float2*)(xr + 512);
        pxg[p] = *(const float2*)(xr + 1024);
        pxo[p] = *(const float2*)(xr + 1536);
    }

    for (int t = 0; t < 512; ++t) {
        const unsigned* hp = t ? (HPbase + (size_t)(t - 1) * 65536) : hp0;
        const unsigned* src = hp + (size_t)(m0 + arow) * 256 + kw;

        // --- stage full K (64 rows x 256 u32) — pure uint4 copy ---
#pragma unroll
        for (int i = 0; i < 16; ++i) {
            const int w = kw + i * 16;               // 0..252
            uint4 v = *(const uint4*)(src + i * 16);
            const int kt2 = w >> 3, wq = w & 7;      // kt 0..31, wq 0 or 4
            AH(kt2, arow, wq)     = v.x;
            AH(kt2, arow, wq + 1) = v.y;
            AH(kt2, arow, wq + 2) = v.z;
            AH(kt2, arow, wq + 3) = v.w;
        }
        __syncthreads();

        float acc[2][2][4];
#pragma unroll
        for (int mf = 0; mf < 2; ++mf)
#pragma unroll
            for (int nf = 0; nf < 2; ++nf)
#pragma unroll
                for (int i = 0; i < 4; ++i) acc[mf][nf][i] = 0.f;

        // --- barrier-free mma loop over all 32 k-tiles (ldmatrix frags) ---
#pragma unroll 4
        for (int kt = 0; kt < 32; ++kt) {
            const uint32_t ko = (uint32_t)kt * 3072u;
            unsigned ah[2][4], bb[4];
            ldsm_x4(ah[0][0], ah[0][1], ah[0][2], ah[0][3], aAddr[0] + ko);
            ldsm_x4(ah[1][0], ah[1][1], ah[1][2], ah[1][3], aAddr[1] + ko);
            ldsm_x4(bb[0], bb[1], bb[2], bb[3], bAddr + ko);
#pragma unroll
            for (int mf = 0; mf < 2; ++mf) {
                mma_f16(acc[mf][0], ah[mf], bb);
                mma_f16(acc[mf][1], ah[mf], bb + 2);
            }
        }
        // no sync needed: Gs is a separate region; As rewritten only after
        // the grid barrier below.

        // --- stage gates into SMEM (Gs) ---
        {
            const int c2 = (lane & 3) * 2;
#pragma unroll
            for (int mf = 0; mf < 2; ++mf)
#pragma unroll
                for (int nf = 0; nf < 2; ++nf) {
                    const int rl = mbw + mf * 16 + r;
                    const int cl = nb0 + nf * 8 + c2;
                    Gs[rl * 65 + cl]           = acc[mf][nf][0];
                    Gs[rl * 65 + cl + 1]       = acc[mf][nf][1];
                    Gs[(rl + 8) * 65 + cl]     = acc[mf][nf][2];
                    Gs[(rl + 8) * 65 + cl + 1] = acc[mf][nf][3];
                }
        }
        __syncthreads();

        // --- gate nonlinearities + c/h update (pure ALU; XP preloaded) ---
        {
            unsigned* hpout = HPbase + (size_t)t * 65536;
#pragma unroll
            for (int p = 0; p < 2; ++p) {
                const int m = mr + p * 32;
                const int b = m0 + m;
                const float* gr = Gs + m * 65 + j2;
                const float i0 = sigf(pxi[p].x + gr[0]);
                const float i1 = sigf(pxi[p].y + gr[1]);
                const float f0 = sigf(pxf[p].x + gr[16]);
                const float f1 = sigf(pxf[p].y + gr[17]);
                const float g0 = tanhf_(pxg[p].x + gr[32]);
                const float g1 = tanhf_(pxg[p].y + gr[33]);
                const float o0 = sigf(pxo[p].x + gr[48]);
                const float o1 = sigf(pxo[p].y + gr[49]);
                const float c0 = f0 * crg[p][0] + i0 * g0;
                const float c1 = f1 * crg[p][1] + i1 * g1;
                crg[p][0] = c0; crg[p][1] = c1;
                const float h0 = o0 * tanhf_(c0);
                const float h1 = o1 * tanhf_(c1);
                hpout[(size_t)b * 256 + ((j0 + j2) >> 1)] = r2h(h0, h1);
            }
        }

        // --- prefetch XP for t+1 (hidden under grid-barrier wait) ---
        if (t + 1 < 512) {
#pragma unroll
            for (int p = 0; p < 2; ++p) {
                const int b = m0 + mr + p * 32;
                const float* xr = XP + (size_t)(t + 1) * 524288
                                + (size_t)b * 2048 + j0 + j2;
                pxi[p] = *(const float2*)(xr);
                pxf[p] = *(const float2*)(xr + 512);
                pxg[p] = *(const float2*)(xr + 1024);
                pxo[p] = *(const float2*)(xr + 1536);
            }
        }

        // --- distributed grid barrier: 32 counters, 4 CTAs each ---
        __threadfence();
        __syncthreads();
        if (tid < 32) {
            if (tid == 0)
                atomicAdd(&bars[(blockIdx.x & 31) * 64], 1u);
            const unsigned target = 4u * (unsigned)(t + 1);
            while (*(volatile unsigned*)&bars[tid * 64] < target) { }
        }
        __syncthreads();
    }
}

// ---------------------------------------------------------------------------
__global__ void reset_bars(unsigned* __restrict__ bars) {
    bars[threadIdx.x * 64] = 0u;   // launched with 32 threads
}

__global__ void final_kernel(
    const unsigned* __restrict__ hlast,   // fp16 h[T-1] slab, row = 256 u32
    const float* __restrict__ Wl, const float* __restrict__ bl,
    float* __restrict__ y)
{
    const int b = blockIdx.x * 8 + (threadIdx.x >> 5);
    const int lane = threadIdx.x & 31;
    const unsigned* hr = hlast + (size_t)b * 256;
    float s = 0.f;
    for (int k = lane; k < 256; k += 32) {
        const __half2 v = *reinterpret_cast<const __half2*>(hr + k);
        s += __half2float(__low2half(v))  * Wl[2 * k]
           + __half2float(__high2half(v)) * Wl[2 * k + 1];
    }
#pragma unroll
    for (int o = 16; o; o >>= 1) s += __shfl_xor_sync(0xffffffffu, s, o);
    if (lane == 0) y[b] = s + bl[0];
}

// ---------------------------------------------------------------------------
extern "C" void kernel_launch(void* const* d_in, const int* in_sizes, int n_in,
                              void* d_out, int out_size)
{
    const float* X     = (const float*)d_in[0];
    const float* W_ih0 = (const float*)d_in[1];
    const float* W_hh0 = (const float*)d_in[2];
    const float* b_ih0 = (const float*)d_in[3];
    const float* b_hh0 = (const float*)d_in[4];
    const float* W_ih1 = (const float*)d_in[5];
    const float* W_hh1 = (const float*)d_in[6];
    const float* b_ih1 = (const float*)d_in[7];
    const float* b_hh1 = (const float*)d_in[8];
    const float* W_lin = (const float*)d_in[9];
    const float* b_lin = (const float*)d_in[10];
    float* y = (float*)d_out;

    float *XP, *Zb;
    unsigned *HPb, *bars;
    cudaGetSymbolAddress((void**)&XP, g_XP);
    cudaGetSymbolAddress((void**)&HPb, g_HP);
    cudaGetSymbolAddress((void**)&Zb, g_Z);
    cudaGetSymbolAddress((void**)&bars, g_bars);

    static bool attr_done = false;
    if (!attr_done) {
        cudaFuncSetAttribute(lstm_persist_kernel,
                             cudaFuncAttributeMaxDynamicSharedMemorySize, PSMEM);
        attr_done = true;
    }

    // Layer 0: proj from fp32 X (X is [B,T,I]: sAb=131072, sAt=256), K=256
    reset_bars<<<1, 32>>>(bars);
    proj_kernel<<<dim3(1024, 32), 256>>>(X, nullptr, 131072, 256, 256,
                                         W_ih0, b_ih0, b_hh0, XP);
    lstm_persist_kernel<<<128, 256, PSMEM>>>((const unsigned*)Zb, W_hh0, XP, HPb, bars);

    // Layer 1: proj from fp16 h, t-major [T,B,H]: sAb=256 u32, sAt=65536 u32
    proj_kernel<<<dim3(1024, 32), 256>>>(nullptr, HPb, 256, 65536, 512,
                                         W_ih1, b_ih1, b_hh1, XP);
    reset_bars<<<1, 32>>>(bars);
    lstm_persist_kernel<<<128, 256, PSMEM>>>((const unsigned*)Zb, W_hh1, XP, HPb, bars);

    final_kernel<<<32, 256>>>(HPb + (size_t)511 * 65536, W_lin, b_lin, y);
}

// round 16
// speedup vs baseline: 2.0604x; 1.1281x over previous
#include <cuda_runtime.h>
#include <cuda_fp16.h>
#include <cstdint>
#include <cstddef>

// Problem sizes: B=256, T=512, I=256, H=512, 4H=2048
// Layouts: g_XP [T,B,4H] fp32, g_HP [T,B,H] fp16 (half2 packed, 2/u32)

__device__ float    g_XP[(size_t)512 * 256 * 2048]; // 1 GiB input projections
__device__ unsigned g_HP[(size_t)512 * 256 * 256];  // fp16 hidden states (2/u32)
__device__ float    g_Z [256 * 512];                // zeros (h_{-1}; any view)
__device__ unsigned g_bars[32 * 64];                // 32 barrier counters, 256B apart

__device__ __forceinline__ unsigned pack2h(__half a, __half b) {
    __half2 t = __halves2half2(a, b);
    return *reinterpret_cast<unsigned*>(&t);
}
__device__ __forceinline__ unsigned r2h(float a, float b) {
    __half2 t = __floats2half2_rn(a, b);
    return *reinterpret_cast<unsigned*>(&t);
}

// Split float4 into hi/lo fp16x2 words (k-even in low half).
__device__ __forceinline__ void split4h(float4 v, unsigned& h0, unsigned& h1,
                                        unsigned& l0, unsigned& l1) {
    __half hx = __float2half(v.x), hy = __float2half(v.y);
    __half hz = __float2half(v.z), hw = __float2half(v.w);
    h0 = pack2h(hx, hy);
    h1 = pack2h(hz, hw);
    l0 = r2h(v.x - __half2float(hx), v.y - __half2float(hy));
    l1 = r2h(v.z - __half2float(hz), v.w - __half2float(hw));
}

__device__ __forceinline__ void mma_f16(float* d, const unsigned* a, const unsigned* b) {
    asm volatile(
        "mma.sync.aligned.m16n8k16.row.col.f32.f16.f16.f32 "
        "{%0,%1,%2,%3}, {%4,%5,%6,%7}, {%8,%9}, {%0,%1,%2,%3};\n"
        : "+f"(d[0]), "+f"(d[1]), "+f"(d[2]), "+f"(d[3])
        : "r"(a[0]), "r"(a[1]), "r"(a[2]), "r"(a[3]), "r"(b[0]), "r"(b[1]));
}

__device__ __forceinline__ void ldsm_x4(unsigned& r0, unsigned& r1,
                                        unsigned& r2, unsigned& r3, unsigned addr) {
    asm volatile("ldmatrix.sync.aligned.m8n8.x4.shared.b16 {%0,%1,%2,%3}, [%4];"
        : "=r"(r0), "=r"(r1), "=r"(r2), "=r"(r3) : "r"(addr));
}
__device__ __forceinline__ uint32_t smem_u32(const void* p) {
    uint32_t a;
    asm("{ .reg .u64 t; cvta.to.shared.u64 t, %1; cvt.u32.u64 %0, t; }" : "=r"(a) : "l"(p));
    return a;
}

// HW tanh: 1 MUFU op (vs EX2+RCP = 2). Max abs err ~2^-10.7.
__device__ __forceinline__ float tanh_fast(float x) {
    float y;
    asm("tanh.approx.f32 %0, %1;" : "=f"(y) : "f"(x));
    return y;
}
// sigmoid(x) = 0.5 + 0.5*tanh(x/2): 1 MUFU + 2 FLOP (vs 2 MUFU).
__device__ __forceinline__ float sigf(float x)   { return fmaf(0.5f, tanh_fast(0.5f * x), 0.5f); }
__device__ __forceinline__ float tanhf_(float x) { return tanh_fast(x); }

// ---------------------------------------------------------------------------
// proj_kernel: out[t,b,0:2048] = A_row(b,t)[0:K] @ W[2048,K]^T + bias1 + bias2
// fp16 2-term (W split hi/lo; A single-rounded). Unchanged (validated R13/R15).
// ---------------------------------------------------------------------------
__global__ void __launch_bounds__(256) proj_kernel(
    const float* __restrict__ Af, const unsigned* __restrict__ Ah,
    int sAb, int sAt, int K,
    const float* __restrict__ W,
    const float* __restrict__ bias1, const float* __restrict__ bias2,
    float* __restrict__ out)
{
    __shared__ unsigned As [2][128][9];
    __shared__ unsigned WsH[2][64][9], WsL[2][64][9];

    const int tid  = threadIdx.x;
    const int lane = tid & 31;
    const int warp = tid >> 5;
    const int wr = warp >> 1, wc = warp & 1;
    const int m0 = blockIdx.x * 128;
    const int bb = m0 >> 9;
    const int tt0 = m0 & 511;
    const int n0 = blockIdx.y * 64;

    const int ar0 = tid >> 2, ac = tid & 3;
    const int wrow = tid >> 2;

    const bool f16a = (Ah != nullptr);
    const float*    Ar0f = Af ? (Af + (size_t)bb * sAb + (size_t)(tt0 + ar0) * sAt + ac * 4) : nullptr;
    const float*    Ar1f = Af ? (Ar0f + (size_t)64 * sAt) : nullptr;
    const unsigned* Ar0h = Ah ? (Ah + (size_t)bb * sAb + (size_t)(tt0 + ar0) * sAt + ac * 2) : nullptr;
    const unsigned* Ar1h = Ah ? (Ar0h + (size_t)64 * sAt) : nullptr;
    const float* Wr = W + (size_t)(n0 + wrow) * K;

    const int nkt = K >> 4;

    float acc[2][4][4];
#pragma unroll
    for (int f = 0; f < 2; ++f)
#pragma unroll
        for (int n = 0; n < 4; ++n)
#pragma unroll
            for (int i = 0; i < 4; ++i) acc[f][n][i] = 0.f;

    float4 ra0, ra1;
    uint2  ua0, ua1;
    float4 rw = *(const float4*)(Wr + ac * 4);
    if (f16a) {
        ua0 = *(const uint2*)(Ar0h);
        ua1 = *(const uint2*)(Ar1h);
        As[0][ar0][2*ac]      = ua0.x; As[0][ar0][2*ac+1]    = ua0.y;
        As[0][ar0+64][2*ac]   = ua1.x; As[0][ar0+64][2*ac+1] = ua1.y;
    } else {
        ra0 = *(const float4*)(Ar0f);
        ra1 = *(const float4*)(Ar1f);
        As[0][ar0][2*ac]      = r2h(ra0.x, ra0.y);
        As[0][ar0][2*ac+1]    = r2h(ra0.z, ra0.w);
        As[0][ar0+64][2*ac]   = r2h(ra1.x, ra1.y);
        As[0][ar0+64][2*ac+1] = r2h(ra1.z, ra1.w);
    }
    {
        unsigned h0, h1, l0, l1;
        split4h(rw, h0, h1, l0, l1);
        WsH[0][wrow][2*ac] = h0; WsH[0][wrow][2*ac+1] = h1;
        WsL[0][wrow][2*ac] = l0; WsL[0][wrow][2*ac+1] = l1;
    }
    __syncthreads();

    int cur = 0;
    for (int kt = 0; kt < nkt; ++kt) {
        const bool pf = (kt + 1 < nkt);
        if (pf) {
            if (f16a) {
                ua0 = *(const uint2*)(Ar0h + (kt + 1) * 8);
                ua1 = *(const uint2*)(Ar1h + (kt + 1) * 8);
            } else {
                ra0 = *(const float4*)(Ar0f + (kt + 1) * 16);
                ra1 = *(const float4*)(Ar1f + (kt + 1) * 16);
            }
            rw = *(const float4*)(Wr + (kt + 1) * 16 + ac * 4);
        }
        const int r = lane >> 2, c = lane & 3;
        unsigned ah[2][4], bh[4][2], bl[4][2];
#pragma unroll
        for (int f = 0; f < 2; ++f) {
            const int mb = wr * 32 + f * 16;
            ah[f][0] = As[cur][mb + r    ][c];
            ah[f][1] = As[cur][mb + r + 8][c];
            ah[f][2] = As[cur][mb + r    ][c + 4];
            ah[f][3] = As[cur][mb + r + 8][c + 4];
        }
#pragma unroll
        for (int n = 0; n < 4; ++n) {
            const int nb = wc * 32 + n * 8 + r;
            bh[n][0] = WsH[cur][nb][c];
            bh[n][1] = WsH[cur][nb][c + 4];
            bl[n][0] = WsL[cur][nb][c];
            bl[n][1] = WsL[cur][nb][c + 4];
        }
#pragma unroll
        for (int f = 0; f < 2; ++f)
#pragma unroll
            for (int n = 0; n < 4; ++n) {
                mma_f16(acc[f][n], ah[f], bh[n]);
                mma_f16(acc[f][n], ah[f], bl[n]);
            }
        if (pf) {
            const int nxt = cur ^ 1;
            if (f16a) {
                As[nxt][ar0][2*ac]      = ua0.x; As[nxt][ar0][2*ac+1]    = ua0.y;
                As[nxt][ar0+64][2*ac]   = ua1.x; As[nxt][ar0+64][2*ac+1] = ua1.y;
            } else {
                As[nxt][ar0][2*ac]      = r2h(ra0.x, ra0.y);
                As[nxt][ar0][2*ac+1]    = r2h(ra0.z, ra0.w);
                As[nxt][ar0+64][2*ac]   = r2h(ra1.x, ra1.y);
                As[nxt][ar0+64][2*ac+1] = r2h(ra1.z, ra1.w);
            }
            unsigned h0, h1, l0, l1;
            split4h(rw, h0, h1, l0, l1);
            WsH[nxt][wrow][2*ac] = h0; WsH[nxt][wrow][2*ac+1] = h1;
            WsL[nxt][wrow][2*ac] = l0; WsL[nxt][wrow][2*ac+1] = l1;
        }
        __syncthreads();
        cur ^= 1;
    }

    const int r = lane >> 2, c2 = (lane & 3) * 2;
#pragma unroll
    for (int f = 0; f < 2; ++f) {
#pragma unroll
        for (int n = 0; n < 4; ++n) {
            const int tloc = tt0 + wr * 32 + f * 16 + r;
            const int col = n0 + wc * 32 + n * 8 + c2;
            const float bb0 = bias1[col] + bias2[col];
            const float bb1 = bias1[col + 1] + bias2[col + 1];
            float* o0 = out + (size_t)tloc * 524288 + (size_t)bb * 2048 + col;
            o0[0]    = acc[f][n][0] + bb0;
            o0[1]    = acc[f][n][1] + bb1;
            float* o1 = out + (size_t)(tloc + 8) * 524288 + (size_t)bb * 2048 + col;
            o1[0]    = acc[f][n][2] + bb0;
            o1[1]    = acc[f][n][3] + bb1;
        }
    }
}

// ---------------------------------------------------------------------------
// lstm_persist_kernel v7: identical structure to v6 (validated R15); ONLY the
// gate nonlinearities changed to tanh.approx-based (5 MUFU/gate-group vs 10).
// 128 CTAs (1/SM), 256 threads (8 warps, 2m x 4n, warp tile 32m x 16n).
// Dynamic SMEM (u32): WsH 24576 + As 24576 + Gs 4160 = 53312 w = 213,248 B.
// ---------------------------------------------------------------------------
#define WH(kt,row,cc) WsH[(kt)*768 + (row)*12 + (cc)]
#define AH(kt,row,cc) As [(kt)*768 + (row)*12 + (cc)]
#define PSMEM (53312 * 4)

__global__ void __launch_bounds__(256) lstm_persist_kernel(
    const unsigned* __restrict__ hp0,  // fp16 h_{-1} (zeros), row = 256 u32
    const float* __restrict__ Whh,     // [2048, 512]
    const float* __restrict__ XP,      // [T,B,4H]
    unsigned* __restrict__ HPbase,     // [T,B,H] fp16, t-slab = 65536 u32
    unsigned* __restrict__ bars)       // 32 counters, stride 64 u32
{
    extern __shared__ unsigned smem_u[];
    unsigned* WsH = smem_u;            // 24576 u32
    unsigned* As  = WsH + 24576;       // 24576 u32
    float*    Gs  = (float*)(As + 24576); // 4160 u32

    const int tid  = threadIdx.x;
    const int lane = tid & 31;
    const int warp = tid >> 5;
    const int mbw = (warp >> 2) * 32;        // warp m base (0/32)
    const int nb0 = (warp & 3) * 16;         // warp n base (0..48)
    const int m0 = (blockIdx.x & 3) * 64;    // batch base
    const int j0 = (blockIdx.x >> 2) * 16;   // hidden-unit base

    const int wl = tid >> 2;                              // local gate col 0..63
    const int ac = tid & 3;
    const int grow = ((wl >> 4) << 9) + j0 + (wl & 15);   // gate row in W_hh

    // --- load W tile into SMEM once (single-rounded fp16) ---
    {
        const float* Wr = Whh + (size_t)grow * 512;
        for (int kt = 0; kt < 32; ++kt) {
            float4 w = *(const float4*)(Wr + kt * 16 + ac * 4);
            WH(kt, wl, 2*ac)   = r2h(w.x, w.y);
            WH(kt, wl, 2*ac+1) = r2h(w.z, w.w);
        }
    }
    __syncthreads();

    // --- ldmatrix per-lane base addresses (byte, shared space) ---
    const uint32_t smW = smem_u32(WsH);
    const uint32_t smA = smem_u32(As);
    const int lq = lane >> 3, lr = lane & 7;
    uint32_t aAddr[2], bAddr;
#pragma unroll
    for (int mf = 0; mf < 2; ++mf) {
        const int row = mbw + mf * 16 + lr + (lq & 1) * 8;
        const int col4 = (lq >> 1) * 4;
        aAddr[mf] = smA + (uint32_t)(row * 12 + col4) * 4u;
    }
    {
        const int row = nb0 + lr + (lq >> 1) * 8;
        const int col4 = (lq & 1) * 4;
        bAddr = smW + (uint32_t)(row * 12 + col4) * 4u;
    }

    const int arow = tid >> 2;                // staging row 0..63
    const int kw = (tid & 3) * 4;             // staging u32-word base
    const int r = lane >> 2;

    // --- epilogue thread mapping (fixed across t) + register state ---
    const int j2 = (tid & 7) * 2;             // 0..14
    const int mr = tid >> 3;                  // 0..31 (m = mr, mr+32)
    float crg[2][2] = {{0.f, 0.f}, {0.f, 0.f}};   // cell state registers
    float2 pxi[2], pxf[2], pxg[2], pxo[2];        // prefetched XP biases

    // prefetch XP for t = 0
#pragma unroll
    for (int p = 0; p < 2; ++p) {
        const int b = m0 + mr + p * 32;
        const float* xr = XP + (size_t)b * 2048 + j0 + j2;
        pxi[p] = *(const float2*)(xr);
        pxf[p] = *(const float2*)(xr + 512);
        pxg[p] = *(const float2*)(xr + 1024);
        pxo[p] = *(const float2*)(xr + 1536);
    }

    for (int t = 0; t < 512; ++t) {
        const unsigned* hp = t ? (HPbase + (size_t)(t - 1) * 65536) : hp0;
        const unsigned* src = hp + (size_t)(m0 + arow) * 256 + kw;

        // --- stage full K (64 rows x 256 u32) — pure uint4 copy ---
#pragma unroll
        for (int i = 0; i < 16; ++i) {
            const int w = kw + i * 16;               // 0..252
            uint4 v = *(const uint4*)(src + i * 16);
            const int kt2 = w >> 3, wq = w & 7;      // kt 0..31, wq 0 or 4
            AH(kt2, arow, wq)     = v.x;
            AH(kt2, arow, wq + 1) = v.y;
            AH(kt2, arow, wq + 2) = v.z;
            AH(kt2, arow, wq + 3) = v.w;
        }
        __syncthreads();

        float acc[2][2][4];
#pragma unroll
        for (int mf = 0; mf < 2; ++mf)
#pragma unroll
            for (int nf = 0; nf < 2; ++nf)
#pragma unroll
                for (int i = 0; i < 4; ++i) acc[mf][nf][i] = 0.f;

        // --- barrier-free mma loop over all 32 k-tiles (ldmatrix frags) ---
#pragma unroll 4
        for (int kt = 0; kt < 32; ++kt) {
            const uint32_t ko = (uint32_t)kt * 3072u;
            unsigned ah[2][4], bb[4];
            ldsm_x4(ah[0][0], ah[0][1], ah[0][2], ah[0][3], aAddr[0] + ko);
            ldsm_x4(ah[1][0], ah[1][1], ah[1][2], ah[1][3], aAddr[1] + ko);
            ldsm_x4(bb[0], bb[1], bb[2], bb[3], bAddr + ko);
#pragma unroll
            for (int mf = 0; mf < 2; ++mf) {
                mma_f16(acc[mf][0], ah[mf], bb);
                mma_f16(acc[mf][1], ah[mf], bb + 2);
            }
        }
        // no sync needed: Gs is a separate region; As rewritten only after
        // the grid barrier below.

        // --- stage gates into SMEM (Gs) ---
        {
            const int c2 = (lane & 3) * 2;
#pragma unroll
            for (int mf = 0; mf < 2; ++mf)
#pragma unroll
                for (int nf = 0; nf < 2; ++nf) {
                    const int rl = mbw + mf * 16 + r;
                    const int cl = nb0 + nf * 8 + c2;
                    Gs[rl * 65 + cl]           = acc[mf][nf][0];
                    Gs[rl * 65 + cl + 1]       = acc[mf][nf][1];
                    Gs[(rl + 8) * 65 + cl]     = acc[mf][nf][2];
                    Gs[(rl + 8) * 65 + cl + 1] = acc[mf][nf][3];
                }
        }
        __syncthreads();

        // --- gate nonlinearities + c/h update (tanh.approx: 5 MUFU/group) ---
        {
            unsigned* hpout = HPbase + (size_t)t * 65536;
#pragma unroll
            for (int p = 0; p < 2; ++p) {
                const int m = mr + p * 32;
                const int b = m0 + m;
                const float* gr = Gs + m * 65 + j2;
                const float i0 = sigf(pxi[p].x + gr[0]);
                const float i1 = sigf(pxi[p].y + gr[1]);
                const float f0 = sigf(pxf[p].x + gr[16]);
                const float f1 = sigf(pxf[p].y + gr[17]);
                const float g0 = tanhf_(pxg[p].x + gr[32]);
                const float g1 = tanhf_(pxg[p].y + gr[33]);
                const float o0 = sigf(pxo[p].x + gr[48]);
                const float o1 = sigf(pxo[p].y + gr[49]);
                const float c0 = f0 * crg[p][0] + i0 * g0;
                const float c1 = f1 * crg[p][1] + i1 * g1;
                crg[p][0] = c0; crg[p][1] = c1;
                const float h0 = o0 * tanhf_(c0);
                const float h1 = o1 * tanhf_(c1);
                hpout[(size_t)b * 256 + ((j0 + j2) >> 1)] = r2h(h0, h1);
            }
        }

        // --- prefetch XP for t+1 (hidden under grid-barrier wait) ---
        if (t + 1 < 512) {
#pragma unroll
            for (int p = 0; p < 2; ++p) {
                const int b = m0 + mr + p * 32;
                const float* xr = XP + (size_t)(t + 1) * 524288
                                + (size_t)b * 2048 + j0 + j2;
                pxi[p] = *(const float2*)(xr);
                pxf[p] = *(const float2*)(xr + 512);
                pxg[p] = *(const float2*)(xr + 1024);
                pxo[p] = *(const float2*)(xr + 1536);
            }
        }

        // --- distributed grid barrier: 32 counters, 4 CTAs each ---
        __threadfence();
        __syncthreads();
        if (tid < 32) {
            if (tid == 0)
                atomicAdd(&bars[(blockIdx.x & 31) * 64], 1u);
            const unsigned target = 4u * (unsigned)(t + 1);
            while (*(volatile unsigned*)&bars[tid * 64] < target) { }
        }
        __syncthreads();
    }
}

// ---------------------------------------------------------------------------
__global__ void reset_bars(unsigned* __restrict__ bars) {
    bars[threadIdx.x * 64] = 0u;   // launched with 32 threads
}

__global__ void final_kernel(
    const unsigned* __restrict__ hlast,   // fp16 h[T-1] slab, row = 256 u32
    const float* __restrict__ Wl, const float* __restrict__ bl,
    float* __restrict__ y)
{
    const int b = blockIdx.x * 8 + (threadIdx.x >> 5);
    const int lane = threadIdx.x & 31;
    const unsigned* hr = hlast + (size_t)b * 256;
    float s = 0.f;
    for (int k = lane; k < 256; k += 32) {
        const __half2 v = *reinterpret_cast<const __half2*>(hr + k);
        s += __half2float(__low2half(v))  * Wl[2 * k]
           + __half2float(__high2half(v)) * Wl[2 * k + 1];
    }
#pragma unroll
    for (int o = 16; o; o >>= 1) s += __shfl_xor_sync(0xffffffffu, s, o);
    if (lane == 0) y[b] = s + bl[0];
}

// ---------------------------------------------------------------------------
extern "C" void kernel_launch(void* const* d_in, const int* in_sizes, int n_in,
                              void* d_out, int out_size)
{
    const float* X     = (const float*)d_in[0];
    const float* W_ih0 = (const float*)d_in[1];
    const float* W_hh0 = (const float*)d_in[2];
    const float* b_ih0 = (const float*)d_in[3];
    const float* b_hh0 = (const float*)d_in[4];
    const float* W_ih1 = (const float*)d_in[5];
    const float* W_hh1 = (const float*)d_in[6];
    const float* b_ih1 = (const float*)d_in[7];
    const float* b_hh1 = (const float*)d_in[8];
    const float* W_lin = (const float*)d_in[9];
    const float* b_lin = (const float*)d_in[10];
    float* y = (float*)d_out;

    float *XP, *Zb;
    unsigned *HPb, *bars;
    cudaGetSymbolAddress((void**)&XP, g_XP);
    cudaGetSymbolAddress((void**)&HPb, g_HP);
    cudaGetSymbolAddress((void**)&Zb, g_Z);
    cudaGetSymbolAddress((void**)&bars, g_bars);

    static bool attr_done = false;
    if (!attr_done) {
        cudaFuncSetAttribute(lstm_persist_kernel,
                             cudaFuncAttributeMaxDynamicSharedMemorySize, PSMEM);
        attr_done = true;
    }

    // Layer 0: proj from fp32 X (X is [B,T,I]: sAb=131072, sAt=256), K=256
    reset_bars<<<1, 32>>>(bars);
    proj_kernel<<<dim3(1024, 32), 256>>>(X, nullptr, 131072, 256, 256,
                                         W_ih0, b_ih0, b_hh0, XP);
    lstm_persist_kernel<<<128, 256, PSMEM>>>((const unsigned*)Zb, W_hh0, XP, HPb, bars);

    // Layer 1: proj from fp16 h, t-major [T,B,H]: sAb=256 u32, sAt=65536 u32
    proj_kernel<<<dim3(1024, 32), 256>>>(nullptr, HPb, 256, 65536, 512,
                                         W_ih1, b_ih1, b_hh1, XP);
    reset_bars<<<1, 32>>>(bars);
    lstm_persist_kernel<<<128, 256, PSMEM>>>((const unsigned*)Zb, W_hh1, XP, HPb, bars);

    final_kernel<<<32, 256>>>(HPb + (size_t)511 * 65536, W_lin, b_lin, y);
}